// round 15
// baseline (speedup 1.0000x reference)
#include <cuda_runtime.h>
#include <cuda_fp16.h>
#include <math.h>
#include <stdint.h>

// Problem constants (GPT_5875515261622)
#define NL   4
#define NH   12
#define EDIM 768
#define TDIM 1024
#define BDIM 2
#define VDIM 50257
#define HD   64
#define BT   (BDIM*TDIM)

// ---- scratch (device globals; no runtime allocation allowed) ----
__device__ float  g_x  [BT*EDIM];
__device__ __half g_h  [BT*EDIM];
__device__ __half g_qkv[BT*3*EDIM];
__device__ __half g_y  [BT*EDIM];
__device__ __half g_m  [BT*4*EDIM];

// fp16 weight copies ([out][in] n-major where transposed)
__device__ __half c_attn_w[NL*EDIM*3*EDIM];
__device__ __half c_atp_w [NL*EDIM*EDIM];
__device__ __half c_fc_w  [NL*EDIM*4*EDIM];
__device__ __half c_pr_w  [NL*4*EDIM*EDIM];
__device__ __half c_wte   [(long long)VDIM*EDIM];

// fast gelu: 0.5u(1+tanh(a)) == u / (1 + exp(-2a)),  a = 0.79788456(u + 0.044715u^3)
__device__ __forceinline__ float gelu_fast(float u) {
    float a = 0.7978845608028654f * (u + 0.044715f * u * u * u);
    return u * __frcp_rn(1.f + __expf(-2.f * a));
}

// ---- fp16 conversion prepass ----
__global__ void half_convert4(const float4* __restrict__ in, __half2* __restrict__ out, int n4) {
    for (int i = blockIdx.x * blockDim.x + threadIdx.x; i < n4; i += gridDim.x * blockDim.x) {
        float4 v = in[i];
        out[2*i]   = __floats2half2_rn(v.x, v.y);
        out[2*i+1] = __floats2half2_rn(v.z, v.w);
    }
}

// ---- transpose + fp16, 64x64 tiles, vectorized both directions ----
__global__ void __launch_bounds__(256)
transpose_half64(const float* __restrict__ in, __half* __restrict__ out,
                 int K, int N) {
    __shared__ float t[64][65];
    long long zoff = (long long)blockIdx.z * K * N;
    in += zoff; out += zoff;
    int n0 = blockIdx.x * 64, k0 = blockIdx.y * 64;
    int x = threadIdx.x & 15, y = threadIdx.x >> 4;   // 16 x 16
    #pragma unroll
    for (int i = 0; i < 4; i++) {
        int kr = y + 16 * i;
        float4 v = *(const float4*)&in[(long long)(k0 + kr) * N + n0 + x * 4];
        t[kr][x * 4 + 0] = v.x; t[kr][x * 4 + 1] = v.y;
        t[kr][x * 4 + 2] = v.z; t[kr][x * 4 + 3] = v.w;
    }
    __syncthreads();
    #pragma unroll
    for (int i = 0; i < 4; i++) {
        int n = y + 16 * i;
        __half2 h0 = __floats2half2_rn(t[x * 4 + 0][n], t[x * 4 + 1][n]);
        __half2 h1 = __floats2half2_rn(t[x * 4 + 2][n], t[x * 4 + 3][n]);
        uint2 pk; pk.x = *(unsigned*)&h0; pk.y = *(unsigned*)&h1;
        *(uint2*)&out[(long long)(n0 + n) * K + k0 + x * 4] = pk;
    }
}

// ---- embedding (vectorized) ----
__global__ void __launch_bounds__(192)
embed_kernel(const int* __restrict__ idx,
             const float* __restrict__ wte,
             const float* __restrict__ wpe) {
    int row = blockIdx.x;
    int t   = row % TDIM;
    long long tok = idx[row];
    const float4* src = (const float4*)(wte + tok * EDIM);
    const float4* pos = (const float4*)(wpe + (long long)t * EDIM);
    float4* dst = (float4*)(g_x + (long long)row * EDIM);
    int c = threadIdx.x;  // 0..191
    float4 a = src[c], p = pos[c];
    a.x += p.x; a.y += p.y; a.z += p.z; a.w += p.w;
    dst[c] = a;
}

// ---- layernorm: one warp per row, single pass, fp32 in -> fp16 out ----
__global__ void __launch_bounds__(256)
layernorm_kernel(const float* __restrict__ in,
                 __half* __restrict__ out,
                 const float* __restrict__ w,
                 const float* __restrict__ b) {
    int warp = threadIdx.x >> 5, lane = threadIdx.x & 31;
    int row = blockIdx.x * 8 + warp;
    const float4* x4 = (const float4*)(in + (long long)row * EDIM);
    float4 v[6];
    float s = 0.f, q = 0.f;
    #pragma unroll
    for (int j = 0; j < 6; j++) {
        v[j] = x4[j * 32 + lane];
        s += v[j].x + v[j].y + v[j].z + v[j].w;
        q += v[j].x * v[j].x + v[j].y * v[j].y + v[j].z * v[j].z + v[j].w * v[j].w;
    }
    #pragma unroll
    for (int o = 16; o > 0; o >>= 1) {
        s += __shfl_xor_sync(0xffffffffu, s, o);
        q += __shfl_xor_sync(0xffffffffu, q, o);
    }
    float mu = s * (1.f / EDIM);
    float var = q * (1.f / EDIM) - mu * mu;
    float rstd = rsqrtf(var + 1e-5f);
    const float4* w4 = (const float4*)w;
    const float4* b4 = (const float4*)b;
    uint2* o8 = (uint2*)(out + (long long)row * EDIM);
    #pragma unroll
    for (int j = 0; j < 6; j++) {
        float4 wv = w4[j * 32 + lane], bv = b4[j * 32 + lane];
        float f0 = (v[j].x - mu) * rstd * wv.x + bv.x;
        float f1 = (v[j].y - mu) * rstd * wv.y + bv.y;
        float f2 = (v[j].z - mu) * rstd * wv.z + bv.z;
        float f3 = (v[j].w - mu) * rstd * wv.w + bv.w;
        __half2 h0 = __floats2half2_rn(f0, f1);
        __half2 h1 = __floats2half2_rn(f2, f3);
        uint2 pk; pk.x = *(unsigned*)&h0; pk.y = *(unsigned*)&h1;
        o8[j * 32 + lane] = pk;
    }
}

// ======================= fused flash attention =======================
#define FLDH 72

__global__ void __launch_bounds__(128, 2)
flash_attn(float scale)
{
    extern __shared__ __half fsm[];
    __half* Qs = fsm;                                  // 128 x FLDH
    const int qb = gridDim.x - 1 - blockIdx.x;         // heavy blocks first
    const int q0 = qb * 128;
    const int z = blockIdx.y;
    const int b = z / NH, h = z % NH;

    const __half* Qg = g_qkv + (long long)b * TDIM * (3 * EDIM) + h * HD;
    const __half* Kg = Qg + EDIM;
    const __half* Vg = Qg + 2 * EDIM;                  // [t][d] rows in g_qkv

    const int tid = threadIdx.x;
    const int warp = tid >> 5, lane = tid & 31;
    const int g = lane >> 2, tg = lane & 3;
    const int quad = lane >> 3, rsel = lane & 7;

    unsigned sQ = (unsigned)__cvta_generic_to_shared(Qs);
    unsigned sK[3] = { sQ + 128u * FLDH * 2u,
                       sQ + (128u + 64u) * FLDH * 2u,
                       sQ + (128u + 128u) * FLDH * 2u };
    unsigned sV[3] = { sQ + (128u + 192u) * FLDH * 2u,
                       sQ + (128u + 256u) * FLDH * 2u,
                       sQ + (128u + 320u) * FLDH * 2u };

    #pragma unroll
    for (int it = 0; it < 8; it++) {
        int idx = tid + it * 128;
        int row = idx >> 3, seg = idx & 7;
        const __half* src = &Qg[(long long)(q0 + row) * (3 * EDIM) + seg * 8];
        unsigned dst = sQ + (unsigned)(row * FLDH + seg * 8) * 2u;
        asm volatile("cp.async.cg.shared.global [%0], [%1], 16;\n" :: "r"(dst), "l"(src));
    }
    auto issueKV = [&](int k0, int buf) {
        #pragma unroll
        for (int it = 0; it < 4; it++) {
            int idx = tid + it * 128;
            int row = idx >> 3, seg = idx & 7;
            const __half* src = &Kg[(long long)(k0 + row) * (3 * EDIM) + seg * 8];
            unsigned dst = sK[buf] + (unsigned)(row * FLDH + seg * 8) * 2u;
            asm volatile("cp.async.cg.shared.global [%0], [%1], 16;\n" :: "r"(dst), "l"(src));
        }
        #pragma unroll
        for (int it = 0; it < 4; it++) {
            int idx = tid + it * 128;
            int row = idx >> 3, seg = idx & 7;
            const __half* src = &Vg[(long long)(k0 + row) * (3 * EDIM) + seg * 8];
            unsigned dst = sV[buf] + (unsigned)(row * FLDH + seg * 8) * 2u;
            asm volatile("cp.async.cg.shared.global [%0], [%1], 16;\n" :: "r"(dst), "l"(src));
        }
        asm volatile("cp.async.commit_group;\n" ::: "memory");
    };

    const int St = 2 * qb + 2;
    issueKV(0, 0);
    issueKV(64, 1);

    unsigned aoffQ[2], boffB[4];
    #pragma unroll
    for (int mt = 0; mt < 2; mt++)
        aoffQ[mt] = (unsigned)(((warp * 32 + mt * 16 + (quad & 1) * 8 + rsel) * FLDH
                                + (quad >> 1) * 8) * 2);
    #pragma unroll
    for (int p = 0; p < 4; p++)
        boffB[p] = (unsigned)(((p * 16 + (quad & 1) * 8 + rsel) * FLDH
                               + (quad >> 1) * 8) * 2);
    unsigned voffB[4];
    #pragma unroll
    for (int p = 0; p < 4; p++)
        voffB[p] = (unsigned)((((quad & 1) * 8 + rsel) * FLDH
                               + p * 16 + (quad >> 1) * 8) * 2);

    float m_s[2][2], l_s[2][2];
    float oacc[2][8][4];
    #pragma unroll
    for (int mt = 0; mt < 2; mt++)
        #pragma unroll
        for (int hp = 0; hp < 2; hp++) { m_s[mt][hp] = -1e30f; l_s[mt][hp] = 0.f; }
    #pragma unroll
    for (int mt = 0; mt < 2; mt++)
        #pragma unroll
        for (int nt = 0; nt < 8; nt++)
            #pragma unroll
            for (int c = 0; c < 4; c++) oacc[mt][nt][c] = 0.f;

    int b0 = 0, b1 = 1, b2 = 2;
    for (int s = 0; s < St; s++) {
        if (s + 1 < St) asm volatile("cp.async.wait_group 1;\n" ::: "memory");
        else            asm volatile("cp.async.wait_group 0;\n" ::: "memory");
        __syncthreads();
        if (s + 2 < St) issueKV((s + 2) * 64, b2);
        const int k0 = s * 64;
        unsigned kb = sK[b0], vb = sV[b0];

        // ---- S = scale * Q @ K^T ----
        float sacc[2][8][4];
        #pragma unroll
        for (int mt = 0; mt < 2; mt++)
            #pragma unroll
            for (int nt = 0; nt < 8; nt++)
                #pragma unroll
                for (int c = 0; c < 4; c++) sacc[mt][nt][c] = 0.f;
        #pragma unroll
        for (int kk = 0; kk < 4; kk++) {
            unsigned af[2][4];
            #pragma unroll
            for (int mt = 0; mt < 2; mt++)
                asm volatile("ldmatrix.sync.aligned.m8n8.x4.shared.b16 {%0,%1,%2,%3}, [%4];"
                             : "=r"(af[mt][0]), "=r"(af[mt][1]), "=r"(af[mt][2]), "=r"(af[mt][3])
                             : "r"(sQ + aoffQ[mt] + (unsigned)(kk * 32)));
            unsigned bf[8][2];
            #pragma unroll
            for (int p = 0; p < 4; p++) {
                unsigned r0, r1, r2, r3;
                asm volatile("ldmatrix.sync.aligned.m8n8.x4.shared.b16 {%0,%1,%2,%3}, [%4];"
                             : "=r"(r0), "=r"(r1), "=r"(r2), "=r"(r3)
                             : "r"(kb + boffB[p] + (unsigned)(kk * 32)));
                bf[2*p][0] = r0;   bf[2*p][1] = r2;
                bf[2*p+1][0] = r1; bf[2*p+1][1] = r3;
            }
            #pragma unroll
            for (int mt = 0; mt < 2; mt++)
                #pragma unroll
                for (int nt = 0; nt < 8; nt++)
                    asm volatile(
                        "mma.sync.aligned.m16n8k16.row.col.f32.f16.f16.f32 "
                        "{%0,%1,%2,%3}, {%4,%5,%6,%7}, {%8,%9}, {%0,%1,%2,%3};\n"
                        : "+f"(sacc[mt][nt][0]), "+f"(sacc[mt][nt][1]),
                          "+f"(sacc[mt][nt][2]), "+f"(sacc[mt][nt][3])
                        : "r"(af[mt][0]), "r"(af[mt][1]), "r"(af[mt][2]), "r"(af[mt][3]),
                          "r"(bf[nt][0]), "r"(bf[nt][1]));
        }

        // ---- scale + causal mask ----
        const int rwb = q0 + warp * 32;
        if (k0 + 63 > rwb) {
            #pragma unroll
            for (int mt = 0; mt < 2; mt++)
                #pragma unroll
                for (int nt = 0; nt < 8; nt++)
                    #pragma unroll
                    for (int c = 0; c < 4; c++) {
                        int r = rwb + mt * 16 + g + ((c >> 1) << 3);
                        int j = k0 + nt * 8 + 2 * tg + (c & 1);
                        sacc[mt][nt][c] = (j > r) ? -1e30f : sacc[mt][nt][c] * scale;
                    }
        } else {
            #pragma unroll
            for (int mt = 0; mt < 2; mt++)
                #pragma unroll
                for (int nt = 0; nt < 8; nt++)
                    #pragma unroll
                    for (int c = 0; c < 4; c++) sacc[mt][nt][c] *= scale;
        }

        // ---- online softmax update ----
        #pragma unroll
        for (int mt = 0; mt < 2; mt++) {
            #pragma unroll
            for (int hp = 0; hp < 2; hp++) {
                float rmax = -1e30f;
                #pragma unroll
                for (int nt = 0; nt < 8; nt++)
                    rmax = fmaxf(rmax, fmaxf(sacc[mt][nt][2*hp], sacc[mt][nt][2*hp+1]));
                rmax = fmaxf(rmax, __shfl_xor_sync(0xffffffffu, rmax, 1));
                rmax = fmaxf(rmax, __shfl_xor_sync(0xffffffffu, rmax, 2));
                float mold = m_s[mt][hp];
                float mnew = fmaxf(mold, rmax);
                float corr = __expf(mold - mnew);
                float rsum = 0.f;
                #pragma unroll
                for (int nt = 0; nt < 8; nt++) {
                    float p0 = __expf(sacc[mt][nt][2*hp]   - mnew);
                    float p1 = __expf(sacc[mt][nt][2*hp+1] - mnew);
                    sacc[mt][nt][2*hp] = p0; sacc[mt][nt][2*hp+1] = p1;
                    rsum += p0 + p1;
                }
                rsum += __shfl_xor_sync(0xffffffffu, rsum, 1);
                rsum += __shfl_xor_sync(0xffffffffu, rsum, 2);
                l_s[mt][hp] = l_s[mt][hp] * corr + rsum;
                m_s[mt][hp] = mnew;
                #pragma unroll
                for (int nt = 0; nt < 8; nt++) {
                    oacc[mt][nt][2*hp]   *= corr;
                    oacc[mt][nt][2*hp+1] *= corr;
                }
            }
        }

        // ---- pack P and O += P @ V (V via ldmatrix.trans) ----
        unsigned pa[2][4][4];
        #pragma unroll
        for (int mt = 0; mt < 2; mt++)
            #pragma unroll
            for (int kk = 0; kk < 4; kk++) {
                __half2 h0 = __floats2half2_rn(sacc[mt][2*kk][0],   sacc[mt][2*kk][1]);
                __half2 h1 = __floats2half2_rn(sacc[mt][2*kk][2],   sacc[mt][2*kk][3]);
                __half2 h2 = __floats2half2_rn(sacc[mt][2*kk+1][0], sacc[mt][2*kk+1][1]);
                __half2 h3 = __floats2half2_rn(sacc[mt][2*kk+1][2], sacc[mt][2*kk+1][3]);
                pa[mt][kk][0] = *(unsigned*)&h0; pa[mt][kk][1] = *(unsigned*)&h1;
                pa[mt][kk][2] = *(unsigned*)&h2; pa[mt][kk][3] = *(unsigned*)&h3;
            }
        #pragma unroll
        for (int kk = 0; kk < 4; kk++) {
            unsigned bf[8][2];
            #pragma unroll
            for (int p = 0; p < 4; p++) {
                unsigned r0, r1, r2, r3;
                asm volatile("ldmatrix.sync.aligned.m8n8.x4.trans.shared.b16 {%0,%1,%2,%3}, [%4];"
                             : "=r"(r0), "=r"(r1), "=r"(r2), "=r"(r3)
                             : "r"(vb + voffB[p] + (unsigned)(kk * 16 * FLDH * 2)));
                bf[2*p][0] = r0;   bf[2*p][1] = r1;
                bf[2*p+1][0] = r2; bf[2*p+1][1] = r3;
            }
            #pragma unroll
            for (int mt = 0; mt < 2; mt++)
                #pragma unroll
                for (int nt = 0; nt < 8; nt++)
                    asm volatile(
                        "mma.sync.aligned.m16n8k16.row.col.f32.f16.f16.f32 "
                        "{%0,%1,%2,%3}, {%4,%5,%6,%7}, {%8,%9}, {%0,%1,%2,%3};\n"
                        : "+f"(oacc[mt][nt][0]), "+f"(oacc[mt][nt][1]),
                          "+f"(oacc[mt][nt][2]), "+f"(oacc[mt][nt][3])
                        : "r"(pa[mt][kk][0]), "r"(pa[mt][kk][1]),
                          "r"(pa[mt][kk][2]), "r"(pa[mt][kk][3]),
                          "r"(bf[nt][0]), "r"(bf[nt][1]));
        }
        int tmp = b0; b0 = b1; b1 = b2; b2 = tmp;
    }

    // ---- normalize, stage through Q smem, coalesced store ----
    #pragma unroll
    for (int mt = 0; mt < 2; mt++) {
        float inv0 = 1.f / l_s[mt][0], inv1 = 1.f / l_s[mt][1];
        #pragma unroll
        for (int nt = 0; nt < 8; nt++) {
            #pragma unroll
            for (int c = 0; c < 4; c++) {
                int rl = warp * 32 + mt * 16 + g + ((c >> 1) << 3);
                int d = nt * 8 + 2 * tg + (c & 1);
                float v = oacc[mt][nt][c] * ((c >> 1) ? inv1 : inv0);
                Qs[rl * FLDH + d] = __float2half_rn(v);
            }
        }
    }
    __syncwarp();
    #pragma unroll
    for (int it = 0; it < 8; it++) {
        int rl = warp * 32 + it * 4 + (lane >> 3);
        int d0 = (lane & 7) * 8;
        uint4 val = *(uint4*)&Qs[rl * FLDH + d0];
        *(uint4*)&g_y[(long long)(b * TDIM + q0 + rl) * EDIM + h * HD + d0] = val;
    }
}
#define SMEM_FA ((128 + 6*64) * FLDH * 2)   // 73728

// ======================= fp16 mma.sync GEMM (3-stage, single sync) =======================
// KS: k-slab width (32 or 64). Smem row stride = KS+8.
template<int NT16, int EP, int OT, int KS>
__global__ void __launch_bounds__(128, (NT16 == 4 || KS == 64) ? 2 : 3)
gemm_fp16(const __half* __restrict__ A, long long sAb, long long sAh,
          const __half* __restrict__ Bm, long long sBb, long long sBh,
          void* __restrict__ Cv, long long sCb, long long sCh,
          const float* __restrict__ bias,
          const float* __restrict__ res,
          int M, int N, int K, int lda, int ldb, int ldc,
          float alpha, int zdiv, int causal)
{
    extern __shared__ char smc[];
    const int LDH = KS + 8;
    const int SEGR = KS / 8;
    const int BROWS = 32 * NT16;
    const int ASTG = 128 * LDH;
    const int BSTG = BROWS * LDH;
    __half* base = (__half*)smc;

    const int m0 = blockIdx.x * 128;
    const int n0 = blockIdx.y * BROWS;
    if (causal && n0 >= m0 + 128) return;

    int z = blockIdx.z;
    int zb = z / zdiv, zh = z % zdiv;
    A  += zb * sAb + zh * sAh;
    Bm += zb * sBb + zh * sBh;
    float* Cf = (float*)Cv + zb * sCb + zh * sCh;
    __half* Ch = (__half*)Cv + zb * sCb + zh * sCh;
    if (EP == 2) res += zb * sCb + zh * sCh;

    const int tid = threadIdx.x;
    const int warp = tid >> 5, lane = tid & 31;
    const int g = lane >> 2, tg = lane & 3;
    const int wm = warp >> 1, wn = warp & 1;
    const int quad = lane >> 3, rsel = lane & 7;

    float acc[4][2 * NT16][4];
    #pragma unroll
    for (int mt = 0; mt < 4; mt++)
        #pragma unroll
        for (int nt = 0; nt < 2 * NT16; nt++)
            #pragma unroll
            for (int c = 0; c < 4; c++) acc[mt][nt][c] = 0.f;

    unsigned aoff[4], boff[NT16];
    #pragma unroll
    for (int mt = 0; mt < 4; mt++)
        aoff[mt] = (unsigned)(((wm * 64 + mt * 16 + (quad & 1) * 8 + rsel) * LDH
                               + (quad >> 1) * 8) * 2);
    #pragma unroll
    for (int p = 0; p < NT16; p++)
        boff[p] = (unsigned)(((wn * 16 * NT16 + p * 16 + (quad & 1) * 8 + rsel) * LDH
                              + (quad >> 1) * 8) * 2);

    unsigned sA[3], sB[3];
    #pragma unroll
    for (int i = 0; i < 3; i++) {
        sA[i] = (unsigned)__cvta_generic_to_shared(base + i * ASTG);
        sB[i] = (unsigned)__cvta_generic_to_shared(base + 3 * ASTG + i * BSTG);
    }

    auto issue = [&](int k0, int buf) {
        unsigned ab = sA[buf], bb = sB[buf];
        #pragma unroll
        for (int it = 0; it < KS / 8; it++) {
            int idx = tid + it * 128;
            int row = idx / SEGR, seg = idx % SEGR;
            const __half* src = &A[(long long)(m0 + row) * lda + k0 + seg * 8];
            unsigned dst = ab + (unsigned)(row * LDH + seg * 8) * 2u;
            asm volatile("cp.async.cg.shared.global [%0], [%1], 16;\n"
                         :: "r"(dst), "l"(src));
        }
        #pragma unroll
        for (int it = 0; it < NT16 * KS / 32; it++) {
            int idx = tid + it * 128;
            int nn = idx / SEGR, seg = idx % SEGR;
            int gn = n0 + nn;
            const __half* src = &Bm[(long long)gn * ldb + k0 + seg * 8];
            int sz = (gn < N) ? 16 : 0;
            if (!sz) src = Bm;
            unsigned dst = bb + (unsigned)(nn * LDH + seg * 8) * 2u;
            asm volatile("cp.async.cg.shared.global [%0], [%1], 16, %2;\n"
                         :: "r"(dst), "l"(src), "r"(sz));
        }
        asm volatile("cp.async.commit_group;\n" ::: "memory");
    };

    const int S = K / KS;
    issue(0, 0);
    if (S > 1) issue(KS, 1);

    int b0 = 0, b1 = 1, b2 = 2;
    for (int s = 0; s < S; s++) {
        if (s + 1 < S) asm volatile("cp.async.wait_group 1;\n" ::: "memory");
        else           asm volatile("cp.async.wait_group 0;\n" ::: "memory");
        __syncthreads();
        if (s + 2 < S) issue((s + 2) * KS, b2);
        unsigned abase = sA[b0], bbase = sB[b0];
        #pragma unroll
        for (int kk = 0; kk < KS / 16; kk++) {
            unsigned af[4][4];
            #pragma unroll
            for (int mt = 0; mt < 4; mt++) {
                asm volatile("ldmatrix.sync.aligned.m8n8.x4.shared.b16 {%0,%1,%2,%3}, [%4];"
                             : "=r"(af[mt][0]), "=r"(af[mt][1]), "=r"(af[mt][2]), "=r"(af[mt][3])
                             : "r"(abase + aoff[mt] + (unsigned)(kk * 32)));
            }
            unsigned bf[2 * NT16][2];
            #pragma unroll
            for (int p = 0; p < NT16; p++) {
                unsigned r0, r1, r2, r3;
                asm volatile("ldmatrix.sync.aligned.m8n8.x4.shared.b16 {%0,%1,%2,%3}, [%4];"
                             : "=r"(r0), "=r"(r1), "=r"(r2), "=r"(r3)
                             : "r"(bbase + boff[p] + (unsigned)(kk * 32)));
                bf[2 * p][0] = r0;     bf[2 * p][1] = r2;
                bf[2 * p + 1][0] = r1; bf[2 * p + 1][1] = r3;
            }
            #pragma unroll
            for (int mt = 0; mt < 4; mt++)
                #pragma unroll
                for (int nt = 0; nt < 2 * NT16; nt++) {
                    asm volatile(
                        "mma.sync.aligned.m16n8k16.row.col.f32.f16.f16.f32 "
                        "{%0,%1,%2,%3}, {%4,%5,%6,%7}, {%8,%9}, {%0,%1,%2,%3};\n"
                        : "+f"(acc[mt][nt][0]), "+f"(acc[mt][nt][1]),
                          "+f"(acc[mt][nt][2]), "+f"(acc[mt][nt][3])
                        : "r"(af[mt][0]), "r"(af[mt][1]), "r"(af[mt][2]), "r"(af[mt][3]),
                          "r"(bf[nt][0]), "r"(bf[nt][1]));
                }
        }
        int tmp = b0; b0 = b1; b1 = b2; b2 = tmp;
    }

    // ---- epilogue: paired stores when ldc even; scalar fallback (logits) ----
    const bool evenldc = ((ldc & 1) == 0);
    #pragma unroll
    for (int mt = 0; mt < 4; mt++) {
        #pragma unroll
        for (int nt = 0; nt < 2 * NT16; nt++) {
            int c = n0 + wn * 16 * NT16 + nt * 8 + 2 * tg;
            int r0 = m0 + wm * 64 + mt * 16 + g;
            #pragma unroll
            for (int hf = 0; hf < 2; hf++) {
                int r = r0 + hf * 8;
                float v0 = alpha * acc[mt][nt][2 * hf];
                float v1 = alpha * acc[mt][nt][2 * hf + 1];
                if (bias) { v0 += __ldg(&bias[c]); v1 += (c + 1 < N) ? __ldg(&bias[c + 1]) : 0.f; }
                if (EP == 1) {
                    v0 = gelu_fast(v0);
                    v1 = gelu_fast(v1);
                }
                if (EP == 2) {
                    v0 += res[(long long)r * ldc + c];
                    if (c + 1 < N) v1 += res[(long long)r * ldc + c + 1];
                }
                if (c + 1 < N && evenldc) {
                    if (OT == 0) {
                        float2 pk = make_float2(v0, v1);
                        *(float2*)&Cf[(long long)r * ldc + c] = pk;
                    } else {
                        __half2 pk = __floats2half2_rn(v0, v1);
                        *(__half2*)&Ch[(long long)r * ldc + c] = pk;
                    }
                } else {
                    if (c < N) {
                        if (OT == 0) Cf[(long long)r * ldc + c] = v0;
                        else         Ch[(long long)r * ldc + c] = __float2half_rn(v0);
                    }
                    if (c + 1 < N) {
                        if (OT == 0) Cf[(long long)r * ldc + c + 1] = v1;
                        else         Ch[(long long)r * ldc + c + 1] = __float2half_rn(v1);
                    }
                }
            }
        }
    }
}

#define SMEM_G(NT16, KS) (3 * ((128 + 32*(NT16)) * ((KS) + 8)) * 2)
#define SMEM_H4_64 SMEM_G(4, 64)   // 110592
#define SMEM_H2_64 SMEM_G(2, 64)   // 82944
#define SMEM_H2_32 SMEM_G(2, 32)   // 46080

extern "C" void kernel_launch(void* const* d_in, const int* in_sizes, int n_in,
                              void* d_out, int out_size) {
    const int*   idx    = (const int*)  d_in[0];
    const float* wte    = (const float*)d_in[1];
    const float* wpe    = (const float*)d_in[2];
    const float* ln1_w  = (const float*)d_in[3];
    const float* ln1_b  = (const float*)d_in[4];
    const float* attn_w = (const float*)d_in[5];
    const float* attn_b = (const float*)d_in[6];
    const float* atp_w  = (const float*)d_in[7];
    const float* atp_b  = (const float*)d_in[8];
    const float* ln2_w  = (const float*)d_in[9];
    const float* ln2_b  = (const float*)d_in[10];
    const float* fc_w   = (const float*)d_in[11];
    const float* fc_b   = (const float*)d_in[12];
    const float* pr_w   = (const float*)d_in[13];
    const float* pr_b   = (const float*)d_in[14];
    const float* lnf_w  = (const float*)d_in[15];
    const float* lnf_b  = (const float*)d_in[16];
    float* out = (float*)d_out;

    float *gx; __half *gh, *gqkv, *gy, *gm;
    __half *cw_attn, *cw_atp, *cw_fc, *cw_pr, *cw_wte;
    cudaGetSymbolAddress((void**)&gx,    g_x);
    cudaGetSymbolAddress((void**)&gh,    g_h);
    cudaGetSymbolAddress((void**)&gqkv,  g_qkv);
    cudaGetSymbolAddress((void**)&gy,    g_y);
    cudaGetSymbolAddress((void**)&gm,    g_m);
    cudaGetSymbolAddress((void**)&cw_attn, c_attn_w);
    cudaGetSymbolAddress((void**)&cw_atp,  c_atp_w);
    cudaGetSymbolAddress((void**)&cw_fc,   c_fc_w);
    cudaGetSymbolAddress((void**)&cw_pr,   c_pr_w);
    cudaGetSymbolAddress((void**)&cw_wte,  c_wte);

    cudaFuncSetAttribute(gemm_fp16<4,0,0,64>, cudaFuncAttributeMaxDynamicSharedMemorySize, SMEM_H4_64);
    cudaFuncSetAttribute(gemm_fp16<4,0,1,64>, cudaFuncAttributeMaxDynamicSharedMemorySize, SMEM_H4_64);
    cudaFuncSetAttribute(gemm_fp16<2,1,1,32>, cudaFuncAttributeMaxDynamicSharedMemorySize, SMEM_H2_32);
    cudaFuncSetAttribute(gemm_fp16<2,2,0,64>, cudaFuncAttributeMaxDynamicSharedMemorySize, SMEM_H2_64);
    cudaFuncSetAttribute(flash_attn, cudaFuncAttributeMaxDynamicSharedMemorySize, SMEM_FA);

    const float scale = 0.03608439182435161f;  // 1/sqrt(E)

    // ---- weight prepass ----
    {
        dim3 b(256);
        transpose_half64<<<dim3(3*EDIM/64, EDIM/64, NL), b>>>(attn_w, cw_attn, EDIM, 3*EDIM);
        transpose_half64<<<dim3(EDIM/64,   EDIM/64, NL), b>>>(atp_w,  cw_atp,  EDIM, EDIM);
        transpose_half64<<<dim3(4*EDIM/64, EDIM/64, NL), b>>>(fc_w,   cw_fc,   EDIM, 4*EDIM);
        transpose_half64<<<dim3(EDIM/64, 4*EDIM/64, NL), b>>>(pr_w,   cw_pr,   4*EDIM, EDIM);
        half_convert4<<<8192, 256>>>((const float4*)wte, (__half2*)cw_wte,
                                     (int)((long long)VDIM*EDIM/4));
    }

    embed_kernel<<<BT, 192>>>(idx, wte, wpe);

    for (int l = 0; l < NL; l++) {
        layernorm_kernel<<<BT/8, 256>>>(gx, gh, ln1_w + l * EDIM, ln1_b + l * EDIM);

        // qkv = h @ attn_w + attn_b  -> half  (KS=64)
        {
            dim3 g(BT / 128, 3 * EDIM / 128, 1);
            gemm_fp16<4, 0, 1, 64><<<g, 128, SMEM_H4_64>>>(gh, 0, 0,
                                      cw_attn + (long long)l * EDIM * 3 * EDIM, 0, 0,
                                      gqkv, 0, 0,
                                      attn_b + l * 3 * EDIM, nullptr,
                                      BT, 3 * EDIM, EDIM, EDIM, EDIM, 3 * EDIM,
                                      1.f, 1, 0);
        }
        // fused attention -> g_y (half)
        flash_attn<<<dim3(TDIM / 128, BDIM * NH), 128, SMEM_FA>>>(scale);

        // x = x + y @ atp_w + atp_b  -> float  (KS=64)
        {
            dim3 g(BT / 128, EDIM / 64, 1);
            gemm_fp16<2, 2, 0, 64><<<g, 128, SMEM_H2_64>>>(gy, 0, 0,
                                      cw_atp + (long long)l * EDIM * EDIM, 0, 0,
                                      gx, 0, 0,
                                      atp_b + l * EDIM, gx,
                                      BT, EDIM, EDIM, EDIM, EDIM, EDIM,
                                      1.f, 1, 0);
        }
        layernorm_kernel<<<BT/8, 256>>>(gx, gh, ln2_w + l * EDIM, ln2_b + l * EDIM);

        // m = gelu(h @ fc_w + fc_b) -> half  (KS=32, occ 3, wave-packed)
        {
            dim3 g(BT / 128, 4 * EDIM / 64, 1);
            gemm_fp16<2, 1, 1, 32><<<g, 128, SMEM_H2_32>>>(gh, 0, 0,
                                      cw_fc + (long long)l * EDIM * 4 * EDIM, 0, 0,
                                      gm, 0, 0,
                                      fc_b + l * 4 * EDIM, nullptr,
                                      BT, 4 * EDIM, EDIM, EDIM, EDIM, 4 * EDIM,
                                      1.f, 1, 0);
        }
        // x = x + m @ pr_w + pr_b  -> float  (KS=64)
        {
            dim3 g(BT / 128, EDIM / 64, 1);
            gemm_fp16<2, 2, 0, 64><<<g, 128, SMEM_H2_64>>>(gm, 0, 0,
                                      cw_pr + (long long)l * 4 * EDIM * EDIM, 0, 0,
                                      gx, 0, 0,
                                      pr_b + l * EDIM, gx,
                                      BT, EDIM, 4 * EDIM, 4 * EDIM, 4 * EDIM, EDIM,
                                      1.f, 1, 0);
        }
    }

    layernorm_kernel<<<BT/8, 256>>>(gx, gh, lnf_w, lnf_b);

    // logits = h @ wte^T -> float  (KS=64; odd ldc -> scalar stores inside)
    {
        dim3 g(BT / 128, (VDIM + 127) / 128, 1);
        gemm_fp16<4, 0, 0, 64><<<g, 128, SMEM_H4_64>>>(gh, 0, 0,
                                  cw_wte, 0, 0,
                                  out, 0, 0,
                                  nullptr, nullptr,
                                  BT, VDIM, EDIM, EDIM, EDIM, VDIM,
                                  1.f, 1, 0);
    }
}

// round 16
// speedup vs baseline: 1.0126x; 1.0126x over previous
#include <cuda_runtime.h>
#include <cuda_fp16.h>
#include <math.h>
#include <stdint.h>

// Problem constants (GPT_5875515261622)
#define NL   4
#define NH   12
#define EDIM 768
#define TDIM 1024
#define BDIM 2
#define VDIM 50257
#define HD   64
#define BT   (BDIM*TDIM)

// ---- scratch (device globals; no runtime allocation allowed) ----
__device__ float  g_x  [BT*EDIM];
__device__ __half g_h  [BT*EDIM];
__device__ __half g_qkv[BT*3*EDIM];
__device__ __half g_y  [BT*EDIM];
__device__ __half g_m  [BT*4*EDIM];

// fp16 weight copies ([out][in] n-major where transposed)
__device__ __half c_attn_w[NL*EDIM*3*EDIM];
__device__ __half c_atp_w [NL*EDIM*EDIM];
__device__ __half c_fc_w  [NL*EDIM*4*EDIM];
__device__ __half c_pr_w  [NL*4*EDIM*EDIM];
__device__ __half c_wte   [(long long)VDIM*EDIM];

// ---- fp16 conversion prepass ----
__global__ void half_convert4(const float4* __restrict__ in, __half2* __restrict__ out, int n4) {
    for (int i = blockIdx.x * blockDim.x + threadIdx.x; i < n4; i += gridDim.x * blockDim.x) {
        float4 v = in[i];
        out[2*i]   = __floats2half2_rn(v.x, v.y);
        out[2*i+1] = __floats2half2_rn(v.z, v.w);
    }
}

// ---- transpose + fp16, 64x64 tiles, vectorized both directions ----
__global__ void __launch_bounds__(256)
transpose_half64(const float* __restrict__ in, __half* __restrict__ out,
                 int K, int N) {
    __shared__ float t[64][65];
    long long zoff = (long long)blockIdx.z * K * N;
    in += zoff; out += zoff;
    int n0 = blockIdx.x * 64, k0 = blockIdx.y * 64;
    int x = threadIdx.x & 15, y = threadIdx.x >> 4;   // 16 x 16
    #pragma unroll
    for (int i = 0; i < 4; i++) {
        int kr = y + 16 * i;
        float4 v = *(const float4*)&in[(long long)(k0 + kr) * N + n0 + x * 4];
        t[kr][x * 4 + 0] = v.x; t[kr][x * 4 + 1] = v.y;
        t[kr][x * 4 + 2] = v.z; t[kr][x * 4 + 3] = v.w;
    }
    __syncthreads();
    #pragma unroll
    for (int i = 0; i < 4; i++) {
        int n = y + 16 * i;
        __half2 h0 = __floats2half2_rn(t[x * 4 + 0][n], t[x * 4 + 1][n]);
        __half2 h1 = __floats2half2_rn(t[x * 4 + 2][n], t[x * 4 + 3][n]);
        uint2 pk; pk.x = *(unsigned*)&h0; pk.y = *(unsigned*)&h1;
        *(uint2*)&out[(long long)(n0 + n) * K + k0 + x * 4] = pk;
    }
}

// ---- embedding (vectorized) ----
__global__ void __launch_bounds__(192)
embed_kernel(const int* __restrict__ idx,
             const float* __restrict__ wte,
             const float* __restrict__ wpe) {
    int row = blockIdx.x;
    int t   = row % TDIM;
    long long tok = idx[row];
    const float4* src = (const float4*)(wte + tok * EDIM);
    const float4* pos = (const float4*)(wpe + (long long)t * EDIM);
    float4* dst = (float4*)(g_x + (long long)row * EDIM);
    int c = threadIdx.x;  // 0..191
    float4 a = src[c], p = pos[c];
    a.x += p.x; a.y += p.y; a.z += p.z; a.w += p.w;
    dst[c] = a;
}

// ---- layernorm: one warp per row, single pass, fp32 in -> fp16 out ----
__global__ void __launch_bounds__(256)
layernorm_kernel(const float* __restrict__ in,
                 __half* __restrict__ out,
                 const float* __restrict__ w,
                 const float* __restrict__ b) {
    int warp = threadIdx.x >> 5, lane = threadIdx.x & 31;
    int row = blockIdx.x * 8 + warp;
    const float4* x4 = (const float4*)(in + (long long)row * EDIM);
    float4 v[6];
    float s = 0.f, q = 0.f;
    #pragma unroll
    for (int j = 0; j < 6; j++) {
        v[j] = x4[j * 32 + lane];
        s += v[j].x + v[j].y + v[j].z + v[j].w;
        q += v[j].x * v[j].x + v[j].y * v[j].y + v[j].z * v[j].z + v[j].w * v[j].w;
    }
    #pragma unroll
    for (int o = 16; o > 0; o >>= 1) {
        s += __shfl_xor_sync(0xffffffffu, s, o);
        q += __shfl_xor_sync(0xffffffffu, q, o);
    }
    float mu = s * (1.f / EDIM);
    float var = q * (1.f / EDIM) - mu * mu;
    float rstd = rsqrtf(var + 1e-5f);
    const float4* w4 = (const float4*)w;
    const float4* b4 = (const float4*)b;
    uint2* o8 = (uint2*)(out + (long long)row * EDIM);
    #pragma unroll
    for (int j = 0; j < 6; j++) {
        float4 wv = w4[j * 32 + lane], bv = b4[j * 32 + lane];
        float f0 = (v[j].x - mu) * rstd * wv.x + bv.x;
        float f1 = (v[j].y - mu) * rstd * wv.y + bv.y;
        float f2 = (v[j].z - mu) * rstd * wv.z + bv.z;
        float f3 = (v[j].w - mu) * rstd * wv.w + bv.w;
        __half2 h0 = __floats2half2_rn(f0, f1);
        __half2 h1 = __floats2half2_rn(f2, f3);
        uint2 pk; pk.x = *(unsigned*)&h0; pk.y = *(unsigned*)&h1;
        o8[j * 32 + lane] = pk;
    }
}

// ======================= fused flash attention =======================
#define FLDH 72

__global__ void __launch_bounds__(128, 2)
flash_attn(float scale)
{
    extern __shared__ __half fsm[];
    __half* Qs = fsm;                                  // 128 x FLDH
    const int qb = gridDim.x - 1 - blockIdx.x;         // heavy blocks first
    const int q0 = qb * 128;
    const int z = blockIdx.y;
    const int b = z / NH, h = z % NH;

    const __half* Qg = g_qkv + (long long)b * TDIM * (3 * EDIM) + h * HD;
    const __half* Kg = Qg + EDIM;
    const __half* Vg = Qg + 2 * EDIM;                  // [t][d] rows in g_qkv

    const int tid = threadIdx.x;
    const int warp = tid >> 5, lane = tid & 31;
    const int g = lane >> 2, tg = lane & 3;
    const int quad = lane >> 3, rsel = lane & 7;

    unsigned sQ = (unsigned)__cvta_generic_to_shared(Qs);
    unsigned sK[3] = { sQ + 128u * FLDH * 2u,
                       sQ + (128u + 64u) * FLDH * 2u,
                       sQ + (128u + 128u) * FLDH * 2u };
    unsigned sV[3] = { sQ + (128u + 192u) * FLDH * 2u,
                       sQ + (128u + 256u) * FLDH * 2u,
                       sQ + (128u + 320u) * FLDH * 2u };

    #pragma unroll
    for (int it = 0; it < 8; it++) {
        int idx = tid + it * 128;
        int row = idx >> 3, seg = idx & 7;
        const __half* src = &Qg[(long long)(q0 + row) * (3 * EDIM) + seg * 8];
        unsigned dst = sQ + (unsigned)(row * FLDH + seg * 8) * 2u;
        asm volatile("cp.async.cg.shared.global [%0], [%1], 16;\n" :: "r"(dst), "l"(src));
    }
    auto issueKV = [&](int k0, int buf) {
        #pragma unroll
        for (int it = 0; it < 4; it++) {
            int idx = tid + it * 128;
            int row = idx >> 3, seg = idx & 7;
            const __half* src = &Kg[(long long)(k0 + row) * (3 * EDIM) + seg * 8];
            unsigned dst = sK[buf] + (unsigned)(row * FLDH + seg * 8) * 2u;
            asm volatile("cp.async.cg.shared.global [%0], [%1], 16;\n" :: "r"(dst), "l"(src));
        }
        #pragma unroll
        for (int it = 0; it < 4; it++) {
            int idx = tid + it * 128;
            int row = idx >> 3, seg = idx & 7;
            const __half* src = &Vg[(long long)(k0 + row) * (3 * EDIM) + seg * 8];
            unsigned dst = sV[buf] + (unsigned)(row * FLDH + seg * 8) * 2u;
            asm volatile("cp.async.cg.shared.global [%0], [%1], 16;\n" :: "r"(dst), "l"(src));
        }
        asm volatile("cp.async.commit_group;\n" ::: "memory");
    };

    const int St = 2 * qb + 2;
    issueKV(0, 0);
    issueKV(64, 1);

    unsigned aoffQ[2], boffB[4];
    #pragma unroll
    for (int mt = 0; mt < 2; mt++)
        aoffQ[mt] = (unsigned)(((warp * 32 + mt * 16 + (quad & 1) * 8 + rsel) * FLDH
                                + (quad >> 1) * 8) * 2);
    #pragma unroll
    for (int p = 0; p < 4; p++)
        boffB[p] = (unsigned)(((p * 16 + (quad & 1) * 8 + rsel) * FLDH
                               + (quad >> 1) * 8) * 2);
    unsigned voffB[4];
    #pragma unroll
    for (int p = 0; p < 4; p++)
        voffB[p] = (unsigned)((((quad & 1) * 8 + rsel) * FLDH
                               + p * 16 + (quad >> 1) * 8) * 2);

    float m_s[2][2], l_s[2][2];
    float oacc[2][8][4];
    #pragma unroll
    for (int mt = 0; mt < 2; mt++)
        #pragma unroll
        for (int hp = 0; hp < 2; hp++) { m_s[mt][hp] = -1e30f; l_s[mt][hp] = 0.f; }
    #pragma unroll
    for (int mt = 0; mt < 2; mt++)
        #pragma unroll
        for (int nt = 0; nt < 8; nt++)
            #pragma unroll
            for (int c = 0; c < 4; c++) oacc[mt][nt][c] = 0.f;

    int b0 = 0, b1 = 1, b2 = 2;
    for (int s = 0; s < St; s++) {
        if (s + 1 < St) asm volatile("cp.async.wait_group 1;\n" ::: "memory");
        else            asm volatile("cp.async.wait_group 0;\n" ::: "memory");
        __syncthreads();
        if (s + 2 < St) issueKV((s + 2) * 64, b2);
        const int k0 = s * 64;
        unsigned kb = sK[b0], vb = sV[b0];

        // ---- S = scale * Q @ K^T ----
        float sacc[2][8][4];
        #pragma unroll
        for (int mt = 0; mt < 2; mt++)
            #pragma unroll
            for (int nt = 0; nt < 8; nt++)
                #pragma unroll
                for (int c = 0; c < 4; c++) sacc[mt][nt][c] = 0.f;
        #pragma unroll
        for (int kk = 0; kk < 4; kk++) {
            unsigned af[2][4];
            #pragma unroll
            for (int mt = 0; mt < 2; mt++)
                asm volatile("ldmatrix.sync.aligned.m8n8.x4.shared.b16 {%0,%1,%2,%3}, [%4];"
                             : "=r"(af[mt][0]), "=r"(af[mt][1]), "=r"(af[mt][2]), "=r"(af[mt][3])
                             : "r"(sQ + aoffQ[mt] + (unsigned)(kk * 32)));
            unsigned bf[8][2];
            #pragma unroll
            for (int p = 0; p < 4; p++) {
                unsigned r0, r1, r2, r3;
                asm volatile("ldmatrix.sync.aligned.m8n8.x4.shared.b16 {%0,%1,%2,%3}, [%4];"
                             : "=r"(r0), "=r"(r1), "=r"(r2), "=r"(r3)
                             : "r"(kb + boffB[p] + (unsigned)(kk * 32)));
                bf[2*p][0] = r0;   bf[2*p][1] = r2;
                bf[2*p+1][0] = r1; bf[2*p+1][1] = r3;
            }
            #pragma unroll
            for (int mt = 0; mt < 2; mt++)
                #pragma unroll
                for (int nt = 0; nt < 8; nt++)
                    asm volatile(
                        "mma.sync.aligned.m16n8k16.row.col.f32.f16.f16.f32 "
                        "{%0,%1,%2,%3}, {%4,%5,%6,%7}, {%8,%9}, {%0,%1,%2,%3};\n"
                        : "+f"(sacc[mt][nt][0]), "+f"(sacc[mt][nt][1]),
                          "+f"(sacc[mt][nt][2]), "+f"(sacc[mt][nt][3])
                        : "r"(af[mt][0]), "r"(af[mt][1]), "r"(af[mt][2]), "r"(af[mt][3]),
                          "r"(bf[nt][0]), "r"(bf[nt][1]));
        }

        // ---- scale + causal mask ----
        const int rwb = q0 + warp * 32;
        if (k0 + 63 > rwb) {
            #pragma unroll
            for (int mt = 0; mt < 2; mt++)
                #pragma unroll
                for (int nt = 0; nt < 8; nt++)
                    #pragma unroll
                    for (int c = 0; c < 4; c++) {
                        int r = rwb + mt * 16 + g + ((c >> 1) << 3);
                        int j = k0 + nt * 8 + 2 * tg + (c & 1);
                        sacc[mt][nt][c] = (j > r) ? -1e30f : sacc[mt][nt][c] * scale;
                    }
        } else {
            #pragma unroll
            for (int mt = 0; mt < 2; mt++)
                #pragma unroll
                for (int nt = 0; nt < 8; nt++)
                    #pragma unroll
                    for (int c = 0; c < 4; c++) sacc[mt][nt][c] *= scale;
        }

        // ---- online softmax update ----
        #pragma unroll
        for (int mt = 0; mt < 2; mt++) {
            #pragma unroll
            for (int hp = 0; hp < 2; hp++) {
                float rmax = -1e30f;
                #pragma unroll
                for (int nt = 0; nt < 8; nt++)
                    rmax = fmaxf(rmax, fmaxf(sacc[mt][nt][2*hp], sacc[mt][nt][2*hp+1]));
                rmax = fmaxf(rmax, __shfl_xor_sync(0xffffffffu, rmax, 1));
                rmax = fmaxf(rmax, __shfl_xor_sync(0xffffffffu, rmax, 2));
                float mold = m_s[mt][hp];
                float mnew = fmaxf(mold, rmax);
                float corr = __expf(mold - mnew);
                float rsum = 0.f;
                #pragma unroll
                for (int nt = 0; nt < 8; nt++) {
                    float p0 = __expf(sacc[mt][nt][2*hp]   - mnew);
                    float p1 = __expf(sacc[mt][nt][2*hp+1] - mnew);
                    sacc[mt][nt][2*hp] = p0; sacc[mt][nt][2*hp+1] = p1;
                    rsum += p0 + p1;
                }
                rsum += __shfl_xor_sync(0xffffffffu, rsum, 1);
                rsum += __shfl_xor_sync(0xffffffffu, rsum, 2);
                l_s[mt][hp] = l_s[mt][hp] * corr + rsum;
                m_s[mt][hp] = mnew;
                #pragma unroll
                for (int nt = 0; nt < 8; nt++) {
                    oacc[mt][nt][2*hp]   *= corr;
                    oacc[mt][nt][2*hp+1] *= corr;
                }
            }
        }

        // ---- pack P and O += P @ V (V via ldmatrix.trans) ----
        unsigned pa[2][4][4];
        #pragma unroll
        for (int mt = 0; mt < 2; mt++)
            #pragma unroll
            for (int kk = 0; kk < 4; kk++) {
                __half2 h0 = __floats2half2_rn(sacc[mt][2*kk][0],   sacc[mt][2*kk][1]);
                __half2 h1 = __floats2half2_rn(sacc[mt][2*kk][2],   sacc[mt][2*kk][3]);
                __half2 h2 = __floats2half2_rn(sacc[mt][2*kk+1][0], sacc[mt][2*kk+1][1]);
                __half2 h3 = __floats2half2_rn(sacc[mt][2*kk+1][2], sacc[mt][2*kk+1][3]);
                pa[mt][kk][0] = *(unsigned*)&h0; pa[mt][kk][1] = *(unsigned*)&h1;
                pa[mt][kk][2] = *(unsigned*)&h2; pa[mt][kk][3] = *(unsigned*)&h3;
            }
        #pragma unroll
        for (int kk = 0; kk < 4; kk++) {
            unsigned bf[8][2];
            #pragma unroll
            for (int p = 0; p < 4; p++) {
                unsigned r0, r1, r2, r3;
                asm volatile("ldmatrix.sync.aligned.m8n8.x4.trans.shared.b16 {%0,%1,%2,%3}, [%4];"
                             : "=r"(r0), "=r"(r1), "=r"(r2), "=r"(r3)
                             : "r"(vb + voffB[p] + (unsigned)(kk * 16 * FLDH * 2)));
                bf[2*p][0] = r0;   bf[2*p][1] = r1;
                bf[2*p+1][0] = r2; bf[2*p+1][1] = r3;
            }
            #pragma unroll
            for (int mt = 0; mt < 2; mt++)
                #pragma unroll
                for (int nt = 0; nt < 8; nt++)
                    asm volatile(
                        "mma.sync.aligned.m16n8k16.row.col.f32.f16.f16.f32 "
                        "{%0,%1,%2,%3}, {%4,%5,%6,%7}, {%8,%9}, {%0,%1,%2,%3};\n"
                        : "+f"(oacc[mt][nt][0]), "+f"(oacc[mt][nt][1]),
                          "+f"(oacc[mt][nt][2]), "+f"(oacc[mt][nt][3])
                        : "r"(pa[mt][kk][0]), "r"(pa[mt][kk][1]),
                          "r"(pa[mt][kk][2]), "r"(pa[mt][kk][3]),
                          "r"(bf[nt][0]), "r"(bf[nt][1]));
        }
        int tmp = b0; b0 = b1; b1 = b2; b2 = tmp;
    }

    // ---- normalize, stage through Q smem, coalesced store ----
    #pragma unroll
    for (int mt = 0; mt < 2; mt++) {
        float inv0 = 1.f / l_s[mt][0], inv1 = 1.f / l_s[mt][1];
        #pragma unroll
        for (int nt = 0; nt < 8; nt++) {
            #pragma unroll
            for (int c = 0; c < 4; c++) {
                int rl = warp * 32 + mt * 16 + g + ((c >> 1) << 3);
                int d = nt * 8 + 2 * tg + (c & 1);
                float v = oacc[mt][nt][c] * ((c >> 1) ? inv1 : inv0);
                Qs[rl * FLDH + d] = __float2half_rn(v);
            }
        }
    }
    __syncwarp();
    #pragma unroll
    for (int it = 0; it < 8; it++) {
        int rl = warp * 32 + it * 4 + (lane >> 3);
        int d0 = (lane & 7) * 8;
        uint4 val = *(uint4*)&Qs[rl * FLDH + d0];
        *(uint4*)&g_y[(long long)(b * TDIM + q0 + rl) * EDIM + h * HD + d0] = val;
    }
}
#define SMEM_FA ((128 + 6*64) * FLDH * 2)   // 73728

// ======================= fp16 mma.sync GEMM (3-stage, single sync) =======================
// KS: k-slab width (32 or 64). Smem row stride = KS+8.
template<int NT16, int EP, int OT, int KS>
__global__ void __launch_bounds__(128, (NT16 == 4 || KS == 64) ? 2 : 3)
gemm_fp16(const __half* __restrict__ A, long long sAb, long long sAh,
          const __half* __restrict__ Bm, long long sBb, long long sBh,
          void* __restrict__ Cv, long long sCb, long long sCh,
          const float* __restrict__ bias,
          const float* __restrict__ res,
          int M, int N, int K, int lda, int ldb, int ldc,
          float alpha, int zdiv, int causal)
{
    extern __shared__ char smc[];
    const int LDH = KS + 8;
    const int SEGR = KS / 8;
    const int BROWS = 32 * NT16;
    const int ASTG = 128 * LDH;
    const int BSTG = BROWS * LDH;
    __half* base = (__half*)smc;

    const int m0 = blockIdx.x * 128;
    const int n0 = blockIdx.y * BROWS;
    if (causal && n0 >= m0 + 128) return;

    int z = blockIdx.z;
    int zb = z / zdiv, zh = z % zdiv;
    A  += zb * sAb + zh * sAh;
    Bm += zb * sBb + zh * sBh;
    float* Cf = (float*)Cv + zb * sCb + zh * sCh;
    __half* Ch = (__half*)Cv + zb * sCb + zh * sCh;
    if (EP == 2) res += zb * sCb + zh * sCh;

    const int tid = threadIdx.x;
    const int warp = tid >> 5, lane = tid & 31;
    const int g = lane >> 2, tg = lane & 3;
    const int wm = warp >> 1, wn = warp & 1;
    const int quad = lane >> 3, rsel = lane & 7;

    float acc[4][2 * NT16][4];
    #pragma unroll
    for (int mt = 0; mt < 4; mt++)
        #pragma unroll
        for (int nt = 0; nt < 2 * NT16; nt++)
            #pragma unroll
            for (int c = 0; c < 4; c++) acc[mt][nt][c] = 0.f;

    unsigned aoff[4], boff[NT16];
    #pragma unroll
    for (int mt = 0; mt < 4; mt++)
        aoff[mt] = (unsigned)(((wm * 64 + mt * 16 + (quad & 1) * 8 + rsel) * LDH
                               + (quad >> 1) * 8) * 2);
    #pragma unroll
    for (int p = 0; p < NT16; p++)
        boff[p] = (unsigned)(((wn * 16 * NT16 + p * 16 + (quad & 1) * 8 + rsel) * LDH
                              + (quad >> 1) * 8) * 2);

    unsigned sA[3], sB[3];
    #pragma unroll
    for (int i = 0; i < 3; i++) {
        sA[i] = (unsigned)__cvta_generic_to_shared(base + i * ASTG);
        sB[i] = (unsigned)__cvta_generic_to_shared(base + 3 * ASTG + i * BSTG);
    }

    auto issue = [&](int k0, int buf) {
        unsigned ab = sA[buf], bb = sB[buf];
        #pragma unroll
        for (int it = 0; it < KS / 8; it++) {
            int idx = tid + it * 128;
            int row = idx / SEGR, seg = idx % SEGR;
            const __half* src = &A[(long long)(m0 + row) * lda + k0 + seg * 8];
            unsigned dst = ab + (unsigned)(row * LDH + seg * 8) * 2u;
            asm volatile("cp.async.cg.shared.global [%0], [%1], 16;\n"
                         :: "r"(dst), "l"(src));
        }
        #pragma unroll
        for (int it = 0; it < NT16 * KS / 32; it++) {
            int idx = tid + it * 128;
            int nn = idx / SEGR, seg = idx % SEGR;
            int gn = n0 + nn;
            const __half* src = &Bm[(long long)gn * ldb + k0 + seg * 8];
            int sz = (gn < N) ? 16 : 0;
            if (!sz) src = Bm;
            unsigned dst = bb + (unsigned)(nn * LDH + seg * 8) * 2u;
            asm volatile("cp.async.cg.shared.global [%0], [%1], 16, %2;\n"
                         :: "r"(dst), "l"(src), "r"(sz));
        }
        asm volatile("cp.async.commit_group;\n" ::: "memory");
    };

    const int S = K / KS;
    issue(0, 0);
    if (S > 1) issue(KS, 1);

    int b0 = 0, b1 = 1, b2 = 2;
    for (int s = 0; s < S; s++) {
        if (s + 1 < S) asm volatile("cp.async.wait_group 1;\n" ::: "memory");
        else           asm volatile("cp.async.wait_group 0;\n" ::: "memory");
        __syncthreads();
        if (s + 2 < S) issue((s + 2) * KS, b2);
        unsigned abase = sA[b0], bbase = sB[b0];
        #pragma unroll
        for (int kk = 0; kk < KS / 16; kk++) {
            unsigned af[4][4];
            #pragma unroll
            for (int mt = 0; mt < 4; mt++) {
                asm volatile("ldmatrix.sync.aligned.m8n8.x4.shared.b16 {%0,%1,%2,%3}, [%4];"
                             : "=r"(af[mt][0]), "=r"(af[mt][1]), "=r"(af[mt][2]), "=r"(af[mt][3])
                             : "r"(abase + aoff[mt] + (unsigned)(kk * 32)));
            }
            unsigned bf[2 * NT16][2];
            #pragma unroll
            for (int p = 0; p < NT16; p++) {
                unsigned r0, r1, r2, r3;
                asm volatile("ldmatrix.sync.aligned.m8n8.x4.shared.b16 {%0,%1,%2,%3}, [%4];"
                             : "=r"(r0), "=r"(r1), "=r"(r2), "=r"(r3)
                             : "r"(bbase + boff[p] + (unsigned)(kk * 32)));
                bf[2 * p][0] = r0;     bf[2 * p][1] = r2;
                bf[2 * p + 1][0] = r1; bf[2 * p + 1][1] = r3;
            }
            #pragma unroll
            for (int mt = 0; mt < 4; mt++)
                #pragma unroll
                for (int nt = 0; nt < 2 * NT16; nt++) {
                    asm volatile(
                        "mma.sync.aligned.m16n8k16.row.col.f32.f16.f16.f32 "
                        "{%0,%1,%2,%3}, {%4,%5,%6,%7}, {%8,%9}, {%0,%1,%2,%3};\n"
                        : "+f"(acc[mt][nt][0]), "+f"(acc[mt][nt][1]),
                          "+f"(acc[mt][nt][2]), "+f"(acc[mt][nt][3])
                        : "r"(af[mt][0]), "r"(af[mt][1]), "r"(af[mt][2]), "r"(af[mt][3]),
                          "r"(bf[nt][0]), "r"(bf[nt][1]));
                }
        }
        int tmp = b0; b0 = b1; b1 = b2; b2 = tmp;
    }

    // ---- epilogue: paired stores when ldc even; scalar fallback (logits) ----
    const bool evenldc = ((ldc & 1) == 0);
    #pragma unroll
    for (int mt = 0; mt < 4; mt++) {
        #pragma unroll
        for (int nt = 0; nt < 2 * NT16; nt++) {
            int c = n0 + wn * 16 * NT16 + nt * 8 + 2 * tg;
            int r0 = m0 + wm * 64 + mt * 16 + g;
            #pragma unroll
            for (int hf = 0; hf < 2; hf++) {
                int r = r0 + hf * 8;
                float v0 = alpha * acc[mt][nt][2 * hf];
                float v1 = alpha * acc[mt][nt][2 * hf + 1];
                if (bias) { v0 += bias[c]; v1 += (c + 1 < N) ? bias[c + 1] : 0.f; }
                if (EP == 1) {
                    float u = v0;
                    v0 = 0.5f * u * (1.f + tanhf(0.7978845608028654f * (u + 0.044715f * u * u * u)));
                    u = v1;
                    v1 = 0.5f * u * (1.f + tanhf(0.7978845608028654f * (u + 0.044715f * u * u * u)));
                }
                if (EP == 2) {
                    v0 += res[(long long)r * ldc + c];
                    if (c + 1 < N) v1 += res[(long long)r * ldc + c + 1];
                }
                if (c + 1 < N && evenldc) {
                    if (OT == 0) {
                        float2 pk = make_float2(v0, v1);
                        *(float2*)&Cf[(long long)r * ldc + c] = pk;
                    } else {
                        __half2 pk = __floats2half2_rn(v0, v1);
                        *(__half2*)&Ch[(long long)r * ldc + c] = pk;
                    }
                } else {
                    if (c < N) {
                        if (OT == 0) Cf[(long long)r * ldc + c] = v0;
                        else         Ch[(long long)r * ldc + c] = __float2half_rn(v0);
                    }
                    if (c + 1 < N) {
                        if (OT == 0) Cf[(long long)r * ldc + c + 1] = v1;
                        else         Ch[(long long)r * ldc + c + 1] = __float2half_rn(v1);
                    }
                }
            }
        }
    }
}

#define SMEM_G(NT16, KS) (3 * ((128 + 32*(NT16)) * ((KS) + 8)) * 2)
#define SMEM_H4_64 SMEM_G(4, 64)   // 110592
#define SMEM_H2_64 SMEM_G(2, 64)   // 82944

extern "C" void kernel_launch(void* const* d_in, const int* in_sizes, int n_in,
                              void* d_out, int out_size) {
    const int*   idx    = (const int*)  d_in[0];
    const float* wte    = (const float*)d_in[1];
    const float* wpe    = (const float*)d_in[2];
    const float* ln1_w  = (const float*)d_in[3];
    const float* ln1_b  = (const float*)d_in[4];
    const float* attn_w = (const float*)d_in[5];
    const float* attn_b = (const float*)d_in[6];
    const float* atp_w  = (const float*)d_in[7];
    const float* atp_b  = (const float*)d_in[8];
    const float* ln2_w  = (const float*)d_in[9];
    const float* ln2_b  = (const float*)d_in[10];
    const float* fc_w   = (const float*)d_in[11];
    const float* fc_b   = (const float*)d_in[12];
    const float* pr_w   = (const float*)d_in[13];
    const float* pr_b   = (const float*)d_in[14];
    const float* lnf_w  = (const float*)d_in[15];
    const float* lnf_b  = (const float*)d_in[16];
    float* out = (float*)d_out;

    float *gx; __half *gh, *gqkv, *gy, *gm;
    __half *cw_attn, *cw_atp, *cw_fc, *cw_pr, *cw_wte;
    cudaGetSymbolAddress((void**)&gx,    g_x);
    cudaGetSymbolAddress((void**)&gh,    g_h);
    cudaGetSymbolAddress((void**)&gqkv,  g_qkv);
    cudaGetSymbolAddress((void**)&gy,    g_y);
    cudaGetSymbolAddress((void**)&gm,    g_m);
    cudaGetSymbolAddress((void**)&cw_attn, c_attn_w);
    cudaGetSymbolAddress((void**)&cw_atp,  c_atp_w);
    cudaGetSymbolAddress((void**)&cw_fc,   c_fc_w);
    cudaGetSymbolAddress((void**)&cw_pr,   c_pr_w);
    cudaGetSymbolAddress((void**)&cw_wte,  c_wte);

    cudaFuncSetAttribute(gemm_fp16<4,0,0,64>, cudaFuncAttributeMaxDynamicSharedMemorySize, SMEM_H4_64);
    cudaFuncSetAttribute(gemm_fp16<4,0,1,64>, cudaFuncAttributeMaxDynamicSharedMemorySize, SMEM_H4_64);
    cudaFuncSetAttribute(gemm_fp16<2,1,1,64>, cudaFuncAttributeMaxDynamicSharedMemorySize, SMEM_H2_64);
    cudaFuncSetAttribute(gemm_fp16<2,2,0,64>, cudaFuncAttributeMaxDynamicSharedMemorySize, SMEM_H2_64);
    cudaFuncSetAttribute(flash_attn, cudaFuncAttributeMaxDynamicSharedMemorySize, SMEM_FA);

    const float scale = 0.03608439182435161f;  // 1/sqrt(E)

    // ---- weight prepass ----
    {
        dim3 b(256);
        transpose_half64<<<dim3(3*EDIM/64, EDIM/64, NL), b>>>(attn_w, cw_attn, EDIM, 3*EDIM);
        transpose_half64<<<dim3(EDIM/64,   EDIM/64, NL), b>>>(atp_w,  cw_atp,  EDIM, EDIM);
        transpose_half64<<<dim3(4*EDIM/64, EDIM/64, NL), b>>>(fc_w,   cw_fc,   EDIM, 4*EDIM);
        transpose_half64<<<dim3(EDIM/64, 4*EDIM/64, NL), b>>>(pr_w,   cw_pr,   4*EDIM, EDIM);
        half_convert4<<<8192, 256>>>((const float4*)wte, (__half2*)cw_wte,
                                     (int)((long long)VDIM*EDIM/4));
    }

    embed_kernel<<<BT, 192>>>(idx, wte, wpe);

    for (int l = 0; l < NL; l++) {
        layernorm_kernel<<<BT/8, 256>>>(gx, gh, ln1_w + l * EDIM, ln1_b + l * EDIM);

        // qkv = h @ attn_w + attn_b  -> half  (KS=64)
        {
            dim3 g(BT / 128, 3 * EDIM / 128, 1);
            gemm_fp16<4, 0, 1, 64><<<g, 128, SMEM_H4_64>>>(gh, 0, 0,
                                      cw_attn + (long long)l * EDIM * 3 * EDIM, 0, 0,
                                      gqkv, 0, 0,
                                      attn_b + l * 3 * EDIM, nullptr,
                                      BT, 3 * EDIM, EDIM, EDIM, EDIM, 3 * EDIM,
                                      1.f, 1, 0);
        }
        // fused attention -> g_y (half)
        flash_attn<<<dim3(TDIM / 128, BDIM * NH), 128, SMEM_FA>>>(scale);

        // x = x + y @ atp_w + atp_b  -> float  (KS=64)
        {
            dim3 g(BT / 128, EDIM / 64, 1);
            gemm_fp16<2, 2, 0, 64><<<g, 128, SMEM_H2_64>>>(gy, 0, 0,
                                      cw_atp + (long long)l * EDIM * EDIM, 0, 0,
                                      gx, 0, 0,
                                      atp_b + l * EDIM, gx,
                                      BT, EDIM, EDIM, EDIM, EDIM, EDIM,
                                      1.f, 1, 0);
        }
        layernorm_kernel<<<BT/8, 256>>>(gx, gh, ln2_w + l * EDIM, ln2_b + l * EDIM);

        // m = gelu(h @ fc_w + fc_b) -> half  (KS=64 test)
        {
            dim3 g(BT / 128, 4 * EDIM / 64, 1);
            gemm_fp16<2, 1, 1, 64><<<g, 128, SMEM_H2_64>>>(gh, 0, 0,
                                      cw_fc + (long long)l * EDIM * 4 * EDIM, 0, 0,
                                      gm, 0, 0,
                                      fc_b + l * 4 * EDIM, nullptr,
                                      BT, 4 * EDIM, EDIM, EDIM, EDIM, 4 * EDIM,
                                      1.f, 1, 0);
        }
        // x = x + m @ pr_w + pr_b  -> float  (KS=64)
        {
            dim3 g(BT / 128, EDIM / 64, 1);
            gemm_fp16<2, 2, 0, 64><<<g, 128, SMEM_H2_64>>>(gm, 0, 0,
                                      cw_pr + (long long)l * 4 * EDIM * EDIM, 0, 0,
                                      gx, 0, 0,
                                      pr_b + l * EDIM, gx,
                                      BT, EDIM, 4 * EDIM, 4 * EDIM, 4 * EDIM, EDIM,
                                      1.f, 1, 0);
        }
    }

    layernorm_kernel<<<BT/8, 256>>>(gx, gh, lnf_w, lnf_b);

    // logits = h @ wte^T -> float  (KS=64; odd ldc -> scalar stores inside)
    {
        dim3 g(BT / 128, (VDIM + 127) / 128, 1);
        gemm_fp16<4, 0, 0, 64><<<g, 128, SMEM_H4_64>>>(gh, 0, 0,
                                  cw_wte, 0, 0,
                                  out, 0, 0,
                                  nullptr, nullptr,
                                  BT, VDIM, EDIM, EDIM, EDIM, VDIM,
                                  1.f, 1, 0);
    }
}

// round 17
// speedup vs baseline: 1.0221x; 1.0094x over previous
#include <cuda_runtime.h>
#include <cuda_fp16.h>
#include <math.h>
#include <stdint.h>

// Problem constants (GPT_5875515261622)
#define NL   4
#define NH   12
#define EDIM 768
#define TDIM 1024
#define BDIM 2
#define VDIM 50257
#define HD   64
#define BT   (BDIM*TDIM)

// ---- scratch (device globals; no runtime allocation allowed) ----
__device__ float  g_x  [BT*EDIM];
__device__ __half g_h  [BT*EDIM];
__device__ __half g_qkv[BT*3*EDIM];
__device__ __half g_y  [BT*EDIM];
__device__ __half g_m  [BT*4*EDIM];

// fp16 weight copies ([out][in] n-major where transposed)
__device__ __half c_attn_w[NL*EDIM*3*EDIM];
__device__ __half c_atp_w [NL*EDIM*EDIM];
__device__ __half c_fc_w  [NL*EDIM*4*EDIM];
__device__ __half c_pr_w  [NL*4*EDIM*EDIM];
__device__ __half c_wte   [(long long)VDIM*EDIM];

// ---- fp16 conversion prepass ----
__global__ void half_convert4(const float4* __restrict__ in, __half2* __restrict__ out, int n4) {
    for (int i = blockIdx.x * blockDim.x + threadIdx.x; i < n4; i += gridDim.x * blockDim.x) {
        float4 v = in[i];
        out[2*i]   = __floats2half2_rn(v.x, v.y);
        out[2*i+1] = __floats2half2_rn(v.z, v.w);
    }
}

// ---- transpose + fp16, 64x64 tiles, vectorized both directions ----
__global__ void __launch_bounds__(256)
transpose_half64(const float* __restrict__ in, __half* __restrict__ out,
                 int K, int N) {
    __shared__ float t[64][65];
    long long zoff = (long long)blockIdx.z * K * N;
    in += zoff; out += zoff;
    int n0 = blockIdx.x * 64, k0 = blockIdx.y * 64;
    int x = threadIdx.x & 15, y = threadIdx.x >> 4;   // 16 x 16
    #pragma unroll
    for (int i = 0; i < 4; i++) {
        int kr = y + 16 * i;
        float4 v = *(const float4*)&in[(long long)(k0 + kr) * N + n0 + x * 4];
        t[kr][x * 4 + 0] = v.x; t[kr][x * 4 + 1] = v.y;
        t[kr][x * 4 + 2] = v.z; t[kr][x * 4 + 3] = v.w;
    }
    __syncthreads();
    #pragma unroll
    for (int i = 0; i < 4; i++) {
        int n = y + 16 * i;
        __half2 h0 = __floats2half2_rn(t[x * 4 + 0][n], t[x * 4 + 1][n]);
        __half2 h1 = __floats2half2_rn(t[x * 4 + 2][n], t[x * 4 + 3][n]);
        uint2 pk; pk.x = *(unsigned*)&h0; pk.y = *(unsigned*)&h1;
        *(uint2*)&out[(long long)(n0 + n) * K + k0 + x * 4] = pk;
    }
}

// ---- embedding (vectorized) ----
__global__ void __launch_bounds__(192)
embed_kernel(const int* __restrict__ idx,
             const float* __restrict__ wte,
             const float* __restrict__ wpe) {
    int row = blockIdx.x;
    int t   = row % TDIM;
    long long tok = idx[row];
    const float4* src = (const float4*)(wte + tok * EDIM);
    const float4* pos = (const float4*)(wpe + (long long)t * EDIM);
    float4* dst = (float4*)(g_x + (long long)row * EDIM);
    int c = threadIdx.x;  // 0..191
    float4 a = src[c], p = pos[c];
    a.x += p.x; a.y += p.y; a.z += p.z; a.w += p.w;
    dst[c] = a;
}

// ---- layernorm: one warp per row, single pass, fp32 in -> fp16 out ----
__global__ void __launch_bounds__(256)
layernorm_kernel(const float* __restrict__ in,
                 __half* __restrict__ out,
                 const float* __restrict__ w,
                 const float* __restrict__ b) {
    int warp = threadIdx.x >> 5, lane = threadIdx.x & 31;
    int row = blockIdx.x * 8 + warp;
    const float4* x4 = (const float4*)(in + (long long)row * EDIM);
    float4 v[6];
    float s = 0.f, q = 0.f;
    #pragma unroll
    for (int j = 0; j < 6; j++) {
        v[j] = x4[j * 32 + lane];
        s += v[j].x + v[j].y + v[j].z + v[j].w;
        q += v[j].x * v[j].x + v[j].y * v[j].y + v[j].z * v[j].z + v[j].w * v[j].w;
    }
    #pragma unroll
    for (int o = 16; o > 0; o >>= 1) {
        s += __shfl_xor_sync(0xffffffffu, s, o);
        q += __shfl_xor_sync(0xffffffffu, q, o);
    }
    float mu = s * (1.f / EDIM);
    float var = q * (1.f / EDIM) - mu * mu;
    float rstd = rsqrtf(var + 1e-5f);
    const float4* w4 = (const float4*)w;
    const float4* b4 = (const float4*)b;
    uint2* o8 = (uint2*)(out + (long long)row * EDIM);
    #pragma unroll
    for (int j = 0; j < 6; j++) {
        float4 wv = w4[j * 32 + lane], bv = b4[j * 32 + lane];
        float f0 = (v[j].x - mu) * rstd * wv.x + bv.x;
        float f1 = (v[j].y - mu) * rstd * wv.y + bv.y;
        float f2 = (v[j].z - mu) * rstd * wv.z + bv.z;
        float f3 = (v[j].w - mu) * rstd * wv.w + bv.w;
        __half2 h0 = __floats2half2_rn(f0, f1);
        __half2 h1 = __floats2half2_rn(f2, f3);
        uint2 pk; pk.x = *(unsigned*)&h0; pk.y = *(unsigned*)&h1;
        o8[j * 32 + lane] = pk;
    }
}

// ======================= fused flash attention =======================
#define FLDH 72

__global__ void __launch_bounds__(128, 2)
flash_attn(float scale)
{
    extern __shared__ __half fsm[];
    __half* Qs = fsm;                                  // 128 x FLDH
    const int qb = gridDim.x - 1 - blockIdx.x;         // heavy blocks first
    const int q0 = qb * 128;
    const int z = blockIdx.y;
    const int b = z / NH, h = z % NH;

    const __half* Qg = g_qkv + (long long)b * TDIM * (3 * EDIM) + h * HD;
    const __half* Kg = Qg + EDIM;
    const __half* Vg = Qg + 2 * EDIM;                  // [t][d] rows in g_qkv

    const int tid = threadIdx.x;
    const int warp = tid >> 5, lane = tid & 31;
    const int g = lane >> 2, tg = lane & 3;
    const int quad = lane >> 3, rsel = lane & 7;

    unsigned sQ = (unsigned)__cvta_generic_to_shared(Qs);
    unsigned sK[3] = { sQ + 128u * FLDH * 2u,
                       sQ + (128u + 64u) * FLDH * 2u,
                       sQ + (128u + 128u) * FLDH * 2u };
    unsigned sV[3] = { sQ + (128u + 192u) * FLDH * 2u,
                       sQ + (128u + 256u) * FLDH * 2u,
                       sQ + (128u + 320u) * FLDH * 2u };

    #pragma unroll
    for (int it = 0; it < 8; it++) {
        int idx = tid + it * 128;
        int row = idx >> 3, seg = idx & 7;
        const __half* src = &Qg[(long long)(q0 + row) * (3 * EDIM) + seg * 8];
        unsigned dst = sQ + (unsigned)(row * FLDH + seg * 8) * 2u;
        asm volatile("cp.async.cg.shared.global [%0], [%1], 16;\n" :: "r"(dst), "l"(src));
    }
    auto issueKV = [&](int k0, int buf) {
        #pragma unroll
        for (int it = 0; it < 4; it++) {
            int idx = tid + it * 128;
            int row = idx >> 3, seg = idx & 7;
            const __half* src = &Kg[(long long)(k0 + row) * (3 * EDIM) + seg * 8];
            unsigned dst = sK[buf] + (unsigned)(row * FLDH + seg * 8) * 2u;
            asm volatile("cp.async.cg.shared.global [%0], [%1], 16;\n" :: "r"(dst), "l"(src));
        }
        #pragma unroll
        for (int it = 0; it < 4; it++) {
            int idx = tid + it * 128;
            int row = idx >> 3, seg = idx & 7;
            const __half* src = &Vg[(long long)(k0 + row) * (3 * EDIM) + seg * 8];
            unsigned dst = sV[buf] + (unsigned)(row * FLDH + seg * 8) * 2u;
            asm volatile("cp.async.cg.shared.global [%0], [%1], 16;\n" :: "r"(dst), "l"(src));
        }
        asm volatile("cp.async.commit_group;\n" ::: "memory");
    };

    const int St = 2 * qb + 2;
    issueKV(0, 0);
    issueKV(64, 1);

    unsigned aoffQ[2], boffB[4];
    #pragma unroll
    for (int mt = 0; mt < 2; mt++)
        aoffQ[mt] = (unsigned)(((warp * 32 + mt * 16 + (quad & 1) * 8 + rsel) * FLDH
                                + (quad >> 1) * 8) * 2);
    #pragma unroll
    for (int p = 0; p < 4; p++)
        boffB[p] = (unsigned)(((p * 16 + (quad & 1) * 8 + rsel) * FLDH
                               + (quad >> 1) * 8) * 2);
    unsigned voffB[4];
    #pragma unroll
    for (int p = 0; p < 4; p++)
        voffB[p] = (unsigned)((((quad & 1) * 8 + rsel) * FLDH
                               + p * 16 + (quad >> 1) * 8) * 2);

    float m_s[2][2], l_s[2][2];
    float oacc[2][8][4];
    #pragma unroll
    for (int mt = 0; mt < 2; mt++)
        #pragma unroll
        for (int hp = 0; hp < 2; hp++) { m_s[mt][hp] = -1e30f; l_s[mt][hp] = 0.f; }
    #pragma unroll
    for (int mt = 0; mt < 2; mt++)
        #pragma unroll
        for (int nt = 0; nt < 8; nt++)
            #pragma unroll
            for (int c = 0; c < 4; c++) oacc[mt][nt][c] = 0.f;

    int b0 = 0, b1 = 1, b2 = 2;
    for (int s = 0; s < St; s++) {
        if (s + 1 < St) asm volatile("cp.async.wait_group 1;\n" ::: "memory");
        else            asm volatile("cp.async.wait_group 0;\n" ::: "memory");
        __syncthreads();
        if (s + 2 < St) issueKV((s + 2) * 64, b2);
        const int k0 = s * 64;
        unsigned kb = sK[b0], vb = sV[b0];

        // ---- S = scale * Q @ K^T ----
        float sacc[2][8][4];
        #pragma unroll
        for (int mt = 0; mt < 2; mt++)
            #pragma unroll
            for (int nt = 0; nt < 8; nt++)
                #pragma unroll
                for (int c = 0; c < 4; c++) sacc[mt][nt][c] = 0.f;
        #pragma unroll
        for (int kk = 0; kk < 4; kk++) {
            unsigned af[2][4];
            #pragma unroll
            for (int mt = 0; mt < 2; mt++)
                asm volatile("ldmatrix.sync.aligned.m8n8.x4.shared.b16 {%0,%1,%2,%3}, [%4];"
                             : "=r"(af[mt][0]), "=r"(af[mt][1]), "=r"(af[mt][2]), "=r"(af[mt][3])
                             : "r"(sQ + aoffQ[mt] + (unsigned)(kk * 32)));
            unsigned bf[8][2];
            #pragma unroll
            for (int p = 0; p < 4; p++) {
                unsigned r0, r1, r2, r3;
                asm volatile("ldmatrix.sync.aligned.m8n8.x4.shared.b16 {%0,%1,%2,%3}, [%4];"
                             : "=r"(r0), "=r"(r1), "=r"(r2), "=r"(r3)
                             : "r"(kb + boffB[p] + (unsigned)(kk * 32)));
                bf[2*p][0] = r0;   bf[2*p][1] = r2;
                bf[2*p+1][0] = r1; bf[2*p+1][1] = r3;
            }
            #pragma unroll
            for (int mt = 0; mt < 2; mt++)
                #pragma unroll
                for (int nt = 0; nt < 8; nt++)
                    asm volatile(
                        "mma.sync.aligned.m16n8k16.row.col.f32.f16.f16.f32 "
                        "{%0,%1,%2,%3}, {%4,%5,%6,%7}, {%8,%9}, {%0,%1,%2,%3};\n"
                        : "+f"(sacc[mt][nt][0]), "+f"(sacc[mt][nt][1]),
                          "+f"(sacc[mt][nt][2]), "+f"(sacc[mt][nt][3])
                        : "r"(af[mt][0]), "r"(af[mt][1]), "r"(af[mt][2]), "r"(af[mt][3]),
                          "r"(bf[nt][0]), "r"(bf[nt][1]));
        }

        // ---- scale + causal mask ----
        const int rwb = q0 + warp * 32;
        if (k0 + 63 > rwb) {
            #pragma unroll
            for (int mt = 0; mt < 2; mt++)
                #pragma unroll
                for (int nt = 0; nt < 8; nt++)
                    #pragma unroll
                    for (int c = 0; c < 4; c++) {
                        int r = rwb + mt * 16 + g + ((c >> 1) << 3);
                        int j = k0 + nt * 8 + 2 * tg + (c & 1);
                        sacc[mt][nt][c] = (j > r) ? -1e30f : sacc[mt][nt][c] * scale;
                    }
        } else {
            #pragma unroll
            for (int mt = 0; mt < 2; mt++)
                #pragma unroll
                for (int nt = 0; nt < 8; nt++)
                    #pragma unroll
                    for (int c = 0; c < 4; c++) sacc[mt][nt][c] *= scale;
        }

        // ---- online softmax update ----
        #pragma unroll
        for (int mt = 0; mt < 2; mt++) {
            #pragma unroll
            for (int hp = 0; hp < 2; hp++) {
                float rmax = -1e30f;
                #pragma unroll
                for (int nt = 0; nt < 8; nt++)
                    rmax = fmaxf(rmax, fmaxf(sacc[mt][nt][2*hp], sacc[mt][nt][2*hp+1]));
                rmax = fmaxf(rmax, __shfl_xor_sync(0xffffffffu, rmax, 1));
                rmax = fmaxf(rmax, __shfl_xor_sync(0xffffffffu, rmax, 2));
                float mold = m_s[mt][hp];
                float mnew = fmaxf(mold, rmax);
                float corr = __expf(mold - mnew);
                float rsum = 0.f;
                #pragma unroll
                for (int nt = 0; nt < 8; nt++) {
                    float p0 = __expf(sacc[mt][nt][2*hp]   - mnew);
                    float p1 = __expf(sacc[mt][nt][2*hp+1] - mnew);
                    sacc[mt][nt][2*hp] = p0; sacc[mt][nt][2*hp+1] = p1;
                    rsum += p0 + p1;
                }
                rsum += __shfl_xor_sync(0xffffffffu, rsum, 1);
                rsum += __shfl_xor_sync(0xffffffffu, rsum, 2);
                l_s[mt][hp] = l_s[mt][hp] * corr + rsum;
                m_s[mt][hp] = mnew;
                #pragma unroll
                for (int nt = 0; nt < 8; nt++) {
                    oacc[mt][nt][2*hp]   *= corr;
                    oacc[mt][nt][2*hp+1] *= corr;
                }
            }
        }

        // ---- pack P and O += P @ V (V via ldmatrix.trans) ----
        unsigned pa[2][4][4];
        #pragma unroll
        for (int mt = 0; mt < 2; mt++)
            #pragma unroll
            for (int kk = 0; kk < 4; kk++) {
                __half2 h0 = __floats2half2_rn(sacc[mt][2*kk][0],   sacc[mt][2*kk][1]);
                __half2 h1 = __floats2half2_rn(sacc[mt][2*kk][2],   sacc[mt][2*kk][3]);
                __half2 h2 = __floats2half2_rn(sacc[mt][2*kk+1][0], sacc[mt][2*kk+1][1]);
                __half2 h3 = __floats2half2_rn(sacc[mt][2*kk+1][2], sacc[mt][2*kk+1][3]);
                pa[mt][kk][0] = *(unsigned*)&h0; pa[mt][kk][1] = *(unsigned*)&h1;
                pa[mt][kk][2] = *(unsigned*)&h2; pa[mt][kk][3] = *(unsigned*)&h3;
            }
        #pragma unroll
        for (int kk = 0; kk < 4; kk++) {
            unsigned bf[8][2];
            #pragma unroll
            for (int p = 0; p < 4; p++) {
                unsigned r0, r1, r2, r3;
                asm volatile("ldmatrix.sync.aligned.m8n8.x4.trans.shared.b16 {%0,%1,%2,%3}, [%4];"
                             : "=r"(r0), "=r"(r1), "=r"(r2), "=r"(r3)
                             : "r"(vb + voffB[p] + (unsigned)(kk * 16 * FLDH * 2)));
                bf[2*p][0] = r0;   bf[2*p][1] = r1;
                bf[2*p+1][0] = r2; bf[2*p+1][1] = r3;
            }
            #pragma unroll
            for (int mt = 0; mt < 2; mt++)
                #pragma unroll
                for (int nt = 0; nt < 8; nt++)
                    asm volatile(
                        "mma.sync.aligned.m16n8k16.row.col.f32.f16.f16.f32 "
                        "{%0,%1,%2,%3}, {%4,%5,%6,%7}, {%8,%9}, {%0,%1,%2,%3};\n"
                        : "+f"(oacc[mt][nt][0]), "+f"(oacc[mt][nt][1]),
                          "+f"(oacc[mt][nt][2]), "+f"(oacc[mt][nt][3])
                        : "r"(pa[mt][kk][0]), "r"(pa[mt][kk][1]),
                          "r"(pa[mt][kk][2]), "r"(pa[mt][kk][3]),
                          "r"(bf[nt][0]), "r"(bf[nt][1]));
        }
        int tmp = b0; b0 = b1; b1 = b2; b2 = tmp;
    }

    // ---- normalize, stage through Q smem, coalesced store ----
    #pragma unroll
    for (int mt = 0; mt < 2; mt++) {
        float inv0 = 1.f / l_s[mt][0], inv1 = 1.f / l_s[mt][1];
        #pragma unroll
        for (int nt = 0; nt < 8; nt++) {
            #pragma unroll
            for (int c = 0; c < 4; c++) {
                int rl = warp * 32 + mt * 16 + g + ((c >> 1) << 3);
                int d = nt * 8 + 2 * tg + (c & 1);
                float v = oacc[mt][nt][c] * ((c >> 1) ? inv1 : inv0);
                Qs[rl * FLDH + d] = __float2half_rn(v);
            }
        }
    }
    __syncwarp();
    #pragma unroll
    for (int it = 0; it < 8; it++) {
        int rl = warp * 32 + it * 4 + (lane >> 3);
        int d0 = (lane & 7) * 8;
        uint4 val = *(uint4*)&Qs[rl * FLDH + d0];
        *(uint4*)&g_y[(long long)(b * TDIM + q0 + rl) * EDIM + h * HD + d0] = val;
    }
}
#define SMEM_FA ((128 + 6*64) * FLDH * 2)   // 73728

// ======================= fp16 mma.sync GEMM (3-stage, single sync) =======================
// KS: k-slab width. ST: 1 -> streaming (evict-first) output stores (logits).
template<int NT16, int EP, int OT, int KS, int ST>
__global__ void __launch_bounds__(128, (NT16 == 4 || KS == 64) ? 2 : 3)
gemm_fp16(const __half* __restrict__ A, long long sAb, long long sAh,
          const __half* __restrict__ Bm, long long sBb, long long sBh,
          void* __restrict__ Cv, long long sCb, long long sCh,
          const float* __restrict__ bias,
          const float* __restrict__ res,
          int M, int N, int K, int lda, int ldb, int ldc,
          float alpha, int zdiv, int causal)
{
    extern __shared__ char smc[];
    const int LDH = KS + 8;
    const int SEGR = KS / 8;
    const int BROWS = 32 * NT16;
    const int ASTG = 128 * LDH;
    const int BSTG = BROWS * LDH;
    __half* base = (__half*)smc;

    const int m0 = blockIdx.x * 128;
    const int n0 = blockIdx.y * BROWS;
    if (causal && n0 >= m0 + 128) return;

    int z = blockIdx.z;
    int zb = z / zdiv, zh = z % zdiv;
    A  += zb * sAb + zh * sAh;
    Bm += zb * sBb + zh * sBh;
    float* Cf = (float*)Cv + zb * sCb + zh * sCh;
    __half* Ch = (__half*)Cv + zb * sCb + zh * sCh;
    if (EP == 2) res += zb * sCb + zh * sCh;

    const int tid = threadIdx.x;
    const int warp = tid >> 5, lane = tid & 31;
    const int g = lane >> 2, tg = lane & 3;
    const int wm = warp >> 1, wn = warp & 1;
    const int quad = lane >> 3, rsel = lane & 7;

    float acc[4][2 * NT16][4];
    #pragma unroll
    for (int mt = 0; mt < 4; mt++)
        #pragma unroll
        for (int nt = 0; nt < 2 * NT16; nt++)
            #pragma unroll
            for (int c = 0; c < 4; c++) acc[mt][nt][c] = 0.f;

    unsigned aoff[4], boff[NT16];
    #pragma unroll
    for (int mt = 0; mt < 4; mt++)
        aoff[mt] = (unsigned)(((wm * 64 + mt * 16 + (quad & 1) * 8 + rsel) * LDH
                               + (quad >> 1) * 8) * 2);
    #pragma unroll
    for (int p = 0; p < NT16; p++)
        boff[p] = (unsigned)(((wn * 16 * NT16 + p * 16 + (quad & 1) * 8 + rsel) * LDH
                              + (quad >> 1) * 8) * 2);

    unsigned sA[3], sB[3];
    #pragma unroll
    for (int i = 0; i < 3; i++) {
        sA[i] = (unsigned)__cvta_generic_to_shared(base + i * ASTG);
        sB[i] = (unsigned)__cvta_generic_to_shared(base + 3 * ASTG + i * BSTG);
    }

    auto issue = [&](int k0, int buf) {
        unsigned ab = sA[buf], bb = sB[buf];
        #pragma unroll
        for (int it = 0; it < KS / 8; it++) {
            int idx = tid + it * 128;
            int row = idx / SEGR, seg = idx % SEGR;
            const __half* src = &A[(long long)(m0 + row) * lda + k0 + seg * 8];
            unsigned dst = ab + (unsigned)(row * LDH + seg * 8) * 2u;
            asm volatile("cp.async.cg.shared.global [%0], [%1], 16;\n"
                         :: "r"(dst), "l"(src));
        }
        #pragma unroll
        for (int it = 0; it < NT16 * KS / 32; it++) {
            int idx = tid + it * 128;
            int nn = idx / SEGR, seg = idx % SEGR;
            int gn = n0 + nn;
            const __half* src = &Bm[(long long)gn * ldb + k0 + seg * 8];
            int sz = (gn < N) ? 16 : 0;
            if (!sz) src = Bm;
            unsigned dst = bb + (unsigned)(nn * LDH + seg * 8) * 2u;
            asm volatile("cp.async.cg.shared.global [%0], [%1], 16, %2;\n"
                         :: "r"(dst), "l"(src), "r"(sz));
        }
        asm volatile("cp.async.commit_group;\n" ::: "memory");
    };

    const int S = K / KS;
    issue(0, 0);
    if (S > 1) issue(KS, 1);

    int b0 = 0, b1 = 1, b2 = 2;
    for (int s = 0; s < S; s++) {
        if (s + 1 < S) asm volatile("cp.async.wait_group 1;\n" ::: "memory");
        else           asm volatile("cp.async.wait_group 0;\n" ::: "memory");
        __syncthreads();
        if (s + 2 < S) issue((s + 2) * KS, b2);
        unsigned abase = sA[b0], bbase = sB[b0];
        #pragma unroll
        for (int kk = 0; kk < KS / 16; kk++) {
            unsigned af[4][4];
            #pragma unroll
            for (int mt = 0; mt < 4; mt++) {
                asm volatile("ldmatrix.sync.aligned.m8n8.x4.shared.b16 {%0,%1,%2,%3}, [%4];"
                             : "=r"(af[mt][0]), "=r"(af[mt][1]), "=r"(af[mt][2]), "=r"(af[mt][3])
                             : "r"(abase + aoff[mt] + (unsigned)(kk * 32)));
            }
            unsigned bf[2 * NT16][2];
            #pragma unroll
            for (int p = 0; p < NT16; p++) {
                unsigned r0, r1, r2, r3;
                asm volatile("ldmatrix.sync.aligned.m8n8.x4.shared.b16 {%0,%1,%2,%3}, [%4];"
                             : "=r"(r0), "=r"(r1), "=r"(r2), "=r"(r3)
                             : "r"(bbase + boff[p] + (unsigned)(kk * 32)));
                bf[2 * p][0] = r0;     bf[2 * p][1] = r2;
                bf[2 * p + 1][0] = r1; bf[2 * p + 1][1] = r3;
            }
            #pragma unroll
            for (int mt = 0; mt < 4; mt++)
                #pragma unroll
                for (int nt = 0; nt < 2 * NT16; nt++) {
                    asm volatile(
                        "mma.sync.aligned.m16n8k16.row.col.f32.f16.f16.f32 "
                        "{%0,%1,%2,%3}, {%4,%5,%6,%7}, {%8,%9}, {%0,%1,%2,%3};\n"
                        : "+f"(acc[mt][nt][0]), "+f"(acc[mt][nt][1]),
                          "+f"(acc[mt][nt][2]), "+f"(acc[mt][nt][3])
                        : "r"(af[mt][0]), "r"(af[mt][1]), "r"(af[mt][2]), "r"(af[mt][3]),
                          "r"(bf[nt][0]), "r"(bf[nt][1]));
                }
        }
        int tmp = b0; b0 = b1; b1 = b2; b2 = tmp;
    }

    // ---- epilogue: paired stores when ldc even; scalar fallback (logits) ----
    const bool evenldc = ((ldc & 1) == 0);
    #pragma unroll
    for (int mt = 0; mt < 4; mt++) {
        #pragma unroll
        for (int nt = 0; nt < 2 * NT16; nt++) {
            int c = n0 + wn * 16 * NT16 + nt * 8 + 2 * tg;
            int r0 = m0 + wm * 64 + mt * 16 + g;
            #pragma unroll
            for (int hf = 0; hf < 2; hf++) {
                int r = r0 + hf * 8;
                float v0 = alpha * acc[mt][nt][2 * hf];
                float v1 = alpha * acc[mt][nt][2 * hf + 1];
                if (bias) { v0 += bias[c]; v1 += (c + 1 < N) ? bias[c + 1] : 0.f; }
                if (EP == 1) {
                    float u = v0;
                    v0 = 0.5f * u * (1.f + tanhf(0.7978845608028654f * (u + 0.044715f * u * u * u)));
                    u = v1;
                    v1 = 0.5f * u * (1.f + tanhf(0.7978845608028654f * (u + 0.044715f * u * u * u)));
                }
                if (EP == 2) {
                    v0 += res[(long long)r * ldc + c];
                    if (c + 1 < N) v1 += res[(long long)r * ldc + c + 1];
                }
                if (c + 1 < N && evenldc) {
                    if (OT == 0) {
                        float2 pk = make_float2(v0, v1);
                        *(float2*)&Cf[(long long)r * ldc + c] = pk;
                    } else {
                        __half2 pk = __floats2half2_rn(v0, v1);
                        *(__half2*)&Ch[(long long)r * ldc + c] = pk;
                    }
                } else {
                    if (c < N) {
                        if (OT == 0) {
                            if (ST) asm volatile("st.global.cs.f32 [%0], %1;"
                                                 :: "l"(&Cf[(long long)r * ldc + c]), "f"(v0) : "memory");
                            else Cf[(long long)r * ldc + c] = v0;
                        } else Ch[(long long)r * ldc + c] = __float2half_rn(v0);
                    }
                    if (c + 1 < N) {
                        if (OT == 0) {
                            if (ST) asm volatile("st.global.cs.f32 [%0], %1;"
                                                 :: "l"(&Cf[(long long)r * ldc + c + 1]), "f"(v1) : "memory");
                            else Cf[(long long)r * ldc + c + 1] = v1;
                        } else Ch[(long long)r * ldc + c + 1] = __float2half_rn(v1);
                    }
                }
            }
        }
    }
}

#define SMEM_G(NT16, KS) (3 * ((128 + 32*(NT16)) * ((KS) + 8)) * 2)
#define SMEM_H4_64 SMEM_G(4, 64)   // 110592
#define SMEM_H2_64 SMEM_G(2, 64)   // 82944
#define SMEM_H2_32 SMEM_G(2, 32)   // 46080

extern "C" void kernel_launch(void* const* d_in, const int* in_sizes, int n_in,
                              void* d_out, int out_size) {
    const int*   idx    = (const int*)  d_in[0];
    const float* wte    = (const float*)d_in[1];
    const float* wpe    = (const float*)d_in[2];
    const float* ln1_w  = (const float*)d_in[3];
    const float* ln1_b  = (const float*)d_in[4];
    const float* attn_w = (const float*)d_in[5];
    const float* attn_b = (const float*)d_in[6];
    const float* atp_w  = (const float*)d_in[7];
    const float* atp_b  = (const float*)d_in[8];
    const float* ln2_w  = (const float*)d_in[9];
    const float* ln2_b  = (const float*)d_in[10];
    const float* fc_w   = (const float*)d_in[11];
    const float* fc_b   = (const float*)d_in[12];
    const float* pr_w   = (const float*)d_in[13];
    const float* pr_b   = (const float*)d_in[14];
    const float* lnf_w  = (const float*)d_in[15];
    const float* lnf_b  = (const float*)d_in[16];
    float* out = (float*)d_out;

    float *gx; __half *gh, *gqkv, *gy, *gm;
    __half *cw_attn, *cw_atp, *cw_fc, *cw_pr, *cw_wte;
    cudaGetSymbolAddress((void**)&gx,    g_x);
    cudaGetSymbolAddress((void**)&gh,    g_h);
    cudaGetSymbolAddress((void**)&gqkv,  g_qkv);
    cudaGetSymbolAddress((void**)&gy,    g_y);
    cudaGetSymbolAddress((void**)&gm,    g_m);
    cudaGetSymbolAddress((void**)&cw_attn, c_attn_w);
    cudaGetSymbolAddress((void**)&cw_atp,  c_atp_w);
    cudaGetSymbolAddress((void**)&cw_fc,   c_fc_w);
    cudaGetSymbolAddress((void**)&cw_pr,   c_pr_w);
    cudaGetSymbolAddress((void**)&cw_wte,  c_wte);

    cudaFuncSetAttribute(gemm_fp16<4,0,0,64,1>, cudaFuncAttributeMaxDynamicSharedMemorySize, SMEM_H4_64);
    cudaFuncSetAttribute(gemm_fp16<4,0,1,64,0>, cudaFuncAttributeMaxDynamicSharedMemorySize, SMEM_H4_64);
    cudaFuncSetAttribute(gemm_fp16<2,1,1,32,0>, cudaFuncAttributeMaxDynamicSharedMemorySize, SMEM_H2_32);
    cudaFuncSetAttribute(gemm_fp16<2,2,0,64,0>, cudaFuncAttributeMaxDynamicSharedMemorySize, SMEM_H2_64);
    cudaFuncSetAttribute(flash_attn, cudaFuncAttributeMaxDynamicSharedMemorySize, SMEM_FA);

    const float scale = 0.03608439182435161f;  // 1/sqrt(E)

    // ---- weight prepass ----
    {
        dim3 b(256);
        transpose_half64<<<dim3(3*EDIM/64, EDIM/64, NL), b>>>(attn_w, cw_attn, EDIM, 3*EDIM);
        transpose_half64<<<dim3(EDIM/64,   EDIM/64, NL), b>>>(atp_w,  cw_atp,  EDIM, EDIM);
        transpose_half64<<<dim3(4*EDIM/64, EDIM/64, NL), b>>>(fc_w,   cw_fc,   EDIM, 4*EDIM);
        transpose_half64<<<dim3(EDIM/64, 4*EDIM/64, NL), b>>>(pr_w,   cw_pr,   4*EDIM, EDIM);
        half_convert4<<<8192, 256>>>((const float4*)wte, (__half2*)cw_wte,
                                     (int)((long long)VDIM*EDIM/4));
    }

    embed_kernel<<<BT, 192>>>(idx, wte, wpe);

    for (int l = 0; l < NL; l++) {
        layernorm_kernel<<<BT/8, 256>>>(gx, gh, ln1_w + l * EDIM, ln1_b + l * EDIM);

        // qkv = h @ attn_w + attn_b  -> half  (KS=64)
        {
            dim3 g(BT / 128, 3 * EDIM / 128, 1);
            gemm_fp16<4, 0, 1, 64, 0><<<g, 128, SMEM_H4_64>>>(gh, 0, 0,
                                      cw_attn + (long long)l * EDIM * 3 * EDIM, 0, 0,
                                      gqkv, 0, 0,
                                      attn_b + l * 3 * EDIM, nullptr,
                                      BT, 3 * EDIM, EDIM, EDIM, EDIM, 3 * EDIM,
                                      1.f, 1, 0);
        }
        // fused attention -> g_y (half)
        flash_attn<<<dim3(TDIM / 128, BDIM * NH), 128, SMEM_FA>>>(scale);

        // x = x + y @ atp_w + atp_b  -> float  (KS=64)
        {
            dim3 g(BT / 128, EDIM / 64, 1);
            gemm_fp16<2, 2, 0, 64, 0><<<g, 128, SMEM_H2_64>>>(gy, 0, 0,
                                      cw_atp + (long long)l * EDIM * EDIM, 0, 0,
                                      gx, 0, 0,
                                      atp_b + l * EDIM, gx,
                                      BT, EDIM, EDIM, EDIM, EDIM, EDIM,
                                      1.f, 1, 0);
        }
        layernorm_kernel<<<BT/8, 256>>>(gx, gh, ln2_w + l * EDIM, ln2_b + l * EDIM);

        // m = gelu(h @ fc_w + fc_b) -> half  (KS=32, occ 3, wave-packed)
        {
            dim3 g(BT / 128, 4 * EDIM / 64, 1);
            gemm_fp16<2, 1, 1, 32, 0><<<g, 128, SMEM_H2_32>>>(gh, 0, 0,
                                      cw_fc + (long long)l * EDIM * 4 * EDIM, 0, 0,
                                      gm, 0, 0,
                                      fc_b + l * 4 * EDIM, nullptr,
                                      BT, 4 * EDIM, EDIM, EDIM, EDIM, 4 * EDIM,
                                      1.f, 1, 0);
        }
        // x = x + m @ pr_w + pr_b  -> float  (KS=64)
        {
            dim3 g(BT / 128, EDIM / 64, 1);
            gemm_fp16<2, 2, 0, 64, 0><<<g, 128, SMEM_H2_64>>>(gm, 0, 0,
                                      cw_pr + (long long)l * 4 * EDIM * EDIM, 0, 0,
                                      gx, 0, 0,
                                      pr_b + l * EDIM, gx,
                                      BT, EDIM, 4 * EDIM, 4 * EDIM, 4 * EDIM, EDIM,
                                      1.f, 1, 0);
        }
    }

    layernorm_kernel<<<BT/8, 256>>>(gx, gh, lnf_w, lnf_b);

    // logits = h @ wte^T -> float  (KS=64; odd ldc -> streaming scalar stores)
    {
        dim3 g(BT / 128, (VDIM + 127) / 128, 1);
        gemm_fp16<4, 0, 0, 64, 1><<<g, 128, SMEM_H4_64>>>(gh, 0, 0,
                                  cw_wte, 0, 0,
                                  out, 0, 0,
                                  nullptr, nullptr,
                                  BT, VDIM, EDIM, EDIM, EDIM, VDIM,
                                  1.f, 1, 0);
    }
}